// round 3
// baseline (speedup 1.0000x reference)
#include <cuda_runtime.h>
#include <math.h>

typedef unsigned long long ull;

#define SS 512
#define NBLK 128

// ---------------- device scratch (no allocations allowed) ----------------
__device__ float g_WTenc[2048 * 4096];   // packed [k][4j+g]; rows 0..1023 = Wih, 1024..2047 = Whh
__device__ float g_WTdec[2048 * 4096];   // same packing
__device__ float g_WTfc [1024 * 1024];   // plain [k][n]
__device__ float g_gatesX[(size_t)64 * 512 * 4096]; // precomputed x@Wih^T (packed cols)
__device__ float g_dA[2][64 * 2048];     // ping-pong: [b][0:1024]=inp, [b][1024:2048]=h
__device__ float g_c [64 * 1024];
__device__ float g_bpe[4096], g_bpd[4096];  // gate-packed biases
__device__ int   g_mask[512];

__device__ unsigned           g_barCount;
__device__ volatile unsigned  g_barGen;

// ---------------- f32x2 helpers ----------------
__device__ __forceinline__ ull dup2(float v) {
    ull r; unsigned u = __float_as_uint(v);
    asm("mov.b64 %0, {%1, %1};" : "=l"(r) : "r"(u));
    return r;
}
__device__ __forceinline__ void fma2(ull& acc, ull a, ull b) {
    asm("fma.rn.f32x2 %0, %1, %2, %0;" : "+l"(acc) : "l"(a), "l"(b));
}
__device__ __forceinline__ float2 unpack2(ull v) {
    unsigned lo, hi;
    asm("mov.b64 {%0, %1}, %2;" : "=r"(lo), "=r"(hi) : "l"(v));
    return make_float2(__uint_as_float(lo), __uint_as_float(hi));
}
__device__ __forceinline__ float sigf(float x) { return 1.0f / (1.0f + expf(-x)); }

// ---------------- grid-wide barrier (all NBLK blocks co-resident) ----------------
__device__ __forceinline__ void grid_sync() {
    __syncthreads();
    if (threadIdx.x == 0) {
        __threadfence();
        unsigned gen = g_barGen;
        if (atomicAdd(&g_barCount, 1u) == NBLK - 1) {
            g_barCount = 0;
            __threadfence();
            g_barGen = gen + 1;
        } else {
            while (g_barGen == gen) { }
        }
        __threadfence();
    }
    __syncthreads();
}

// ---- A tile staging: 64m x 32k, coalesced loads, XOR-swizzled conflict-free store ----
// layout: As[k*64 + (chunk(m) ^ (k>>2))*4 + (m&3)], chunk(m)=m>>2 (16 chunks)
__device__ __forceinline__ void loadA(const float* __restrict__ A, int lda, int kOff,
                                      float4 pa[2], int tid)
{
    const int k4 = tid & 7;           // float4 index along k
    const int mA = tid >> 3;          // 0..31
#pragma unroll
    for (int i = 0; i < 2; ++i)
        pa[i] = *(const float4*)(A + (size_t)(mA + 32 * i) * lda + kOff + k4 * 4);
}
__device__ __forceinline__ void storeA(float* As, const float4 pa[2], int tid)
{
    const int k4 = tid & 7;
    const int mA = tid >> 3;
#pragma unroll
    for (int i = 0; i < 2; ++i) {
        int m  = mA + 32 * i;
        int cm = m >> 2;
        const float* e = (const float*)&pa[i];
#pragma unroll
        for (int r = 0; r < 4; ++r) {
            int k = k4 * 4 + r;
            As[k * 64 + ((cm ^ (k >> 2)) << 2) + (m & 3)] = e[r];
        }
    }
}

// ---------------- gate GEMM (persistent): C_tile 64m x 32n', full K, fused accum ----
// per-thread: ty=tid>>5 -> m0=8*ty (4 m-pairs), tx=tid&31 -> 1 packed column
__device__ __forceinline__ void gemm_gate(const float* __restrict__ A, int lda,
                                          const float* __restrict__ Wp,   // + nBase, ldw=4096
                                          int K, ull acc[4],
                                          float* As, float* Ws, int tid)
{
    const int ty = tid >> 5, tx = tid & 31;
    const int wk = tid >> 3, wc = tid & 7;   // W staging: k row, float4 col
#pragma unroll
    for (int i = 0; i < 4; ++i) acc[i] = 0ull;

    float4 pa[2], pw;
    loadA(A, lda, 0, pa, tid);
    pw = *(const float4*)(Wp + (size_t)wk * 4096 + wc * 4);

    for (int kt = 0; kt < K; kt += 32) {
        storeA(As, pa, tid);
        *(float4*)&Ws[wk * 32 + wc * 4] = pw;
        __syncthreads();
        if (kt + 32 < K) {
            loadA(A, lda, kt + 32, pa, tid);
            pw = *(const float4*)(Wp + (size_t)(kt + 32 + wk) * 4096 + wc * 4);
        }
#pragma unroll
        for (int kk = 0; kk < 32; ++kk) {
            int sw = kk >> 2;
            ulonglong2 aa = *(const ulonglong2*)&As[kk * 64 + (((2 * ty)     ^ sw) << 2)];
            ulonglong2 ab = *(const ulonglong2*)&As[kk * 64 + ((((2 * ty) | 1) ^ sw) << 2)];
            ull w = dup2(Ws[kk * 32 + tx]);
            fma2(acc[0], aa.x, w); fma2(acc[1], aa.y, w);
            fma2(acc[2], ab.x, w); fma2(acc[3], ab.y, w);
        }
        __syncthreads();
    }
}

// ---------------- fc GEMM (persistent): C_tile 64m x 8n, K=1024 ----
// per-thread: ty=tid>>3 (0..31) -> m-pair (2ty,2ty+1), tx=tid&7 -> 1 column
__device__ __forceinline__ void gemm_fc(const float* __restrict__ A, int lda,
                                        const float* __restrict__ Wp,   // + n0, ldw=1024
                                        ull& acc, float* As, float* Ws, int tid)
{
    const int ty = tid >> 3, tx = tid & 7;
    acc = 0ull;
    float4 pa[2], pw;
    loadA(A, lda, 0, pa, tid);
    if (tid < 64) pw = *(const float4*)(Wp + (size_t)(tid >> 1) * 1024 + (tid & 1) * 4);

    for (int kt = 0; kt < 1024; kt += 32) {
        storeA(As, pa, tid);
        if (tid < 64) *(float4*)&Ws[(tid >> 1) * 8 + (tid & 1) * 4] = pw;
        __syncthreads();
        if (kt + 32 < 1024) {
            loadA(A, lda, kt + 32, pa, tid);
            if (tid < 64) pw = *(const float4*)(Wp + (size_t)(kt + 32 + (tid >> 1)) * 1024 + (tid & 1) * 4);
        }
#pragma unroll
        for (int kk = 0; kk < 32; ++kk) {
            int sw = kk >> 2;
            ull a = *(const ull*)&As[kk * 64 + (((ty >> 1) ^ sw) << 2) + ((ty & 1) << 1)];
            ull w = dup2(Ws[kk * 8 + tx]);
            fma2(acc, a, w);
        }
        __syncthreads();
    }
}

// ============ the persistent seq2seq kernel ============
__global__ __launch_bounds__(256, 1)
void seq2seq_persist(const float* __restrict__ x, const float* __restrict__ target,
                     const float* __restrict__ fc_b, float* __restrict__ out)
{
    __shared__ float As[32 * 64];
    __shared__ float Ws[32 * 32];
    __shared__ float sG[32][65];

    const int tid = threadIdx.x;
    const int bid = blockIdx.x;
    const int ty = tid >> 5, tx = tid & 31;
    const int m0 = ty * 8;
    int cur = 0;

    // ---------------- encoder ----------------
    for (int t = 0; t < SS; ++t) {
        ull acc[4];
        gemm_gate(g_dA[cur] + 1024, 2048,
                  g_WTenc + (size_t)1024 * 4096 + bid * 32, 1024, acc, As, Ws, tid);
#pragma unroll
        for (int p = 0; p < 4; ++p) {
            float2 v = unpack2(acc[p]);
            sG[tx][m0 + 2 * p]     = v.x;
            sG[tx][m0 + 2 * p + 1] = v.y;
        }
        __syncthreads();
#pragma unroll
        for (int r = 0; r < 2; ++r) {
            int id = tid + 256 * r;
            int b = id & 63, jj = id >> 6;
            int j = (bid << 3) + jj;
            float4 gx = *(const float4*)&g_gatesX[((size_t)b * SS + t) * 4096 + (bid << 5) + (jj << 2)];
            float4 bb = *(const float4*)&g_bpe[(bid << 5) + (jj << 2)];
            float gi = sG[4 * jj + 0][b] + gx.x + bb.x;
            float gf = sG[4 * jj + 1][b] + gx.y + bb.y;
            float gg = sG[4 * jj + 2][b] + gx.z + bb.z;
            float go = sG[4 * jj + 3][b] + gx.w + bb.w;
            float c  = g_c[b * 1024 + j];
            float cn = sigf(gf) * c + sigf(gi) * tanhf(gg);
            float hn = sigf(go) * tanhf(cn);
            g_c[b * 1024 + j] = cn;
            g_dA[cur ^ 1][b * 2048 + 1024 + j] = hn;
            if (t == SS - 1)   // stage dec_inp0 = x[:, -1, :]
                g_dA[cur ^ 1][b * 2048 + j] = x[((size_t)b * SS + SS - 1) * 1024 + j];
        }
        grid_sync();
        cur ^= 1;
    }

    // ---------------- decoder ----------------
    for (int t = 0; t < SS; ++t) {
        ull acc[4];
        gemm_gate(g_dA[cur], 2048, g_WTdec + bid * 32, 2048, acc, As, Ws, tid);
#pragma unroll
        for (int p = 0; p < 4; ++p) {
            float2 v = unpack2(acc[p]);
            sG[tx][m0 + 2 * p]     = v.x;
            sG[tx][m0 + 2 * p + 1] = v.y;
        }
        __syncthreads();
#pragma unroll
        for (int r = 0; r < 2; ++r) {
            int id = tid + 256 * r;
            int b = id & 63, jj = id >> 6;
            int j = (bid << 3) + jj;
            float4 bb = *(const float4*)&g_bpd[(bid << 5) + (jj << 2)];
            float gi = sG[4 * jj + 0][b] + bb.x;
            float gf = sG[4 * jj + 1][b] + bb.y;
            float gg = sG[4 * jj + 2][b] + bb.z;
            float go = sG[4 * jj + 3][b] + bb.w;
            float c  = g_c[b * 1024 + j];
            float cn = sigf(gf) * c + sigf(gi) * tanhf(gg);
            float hn = sigf(go) * tanhf(cn);
            g_c[b * 1024 + j] = cn;
            g_dA[cur ^ 1][b * 2048 + 1024 + j] = hn;
        }
        grid_sync();   // all h written before fc reads full K

        ull fa;
        gemm_fc(g_dA[cur ^ 1] + 1024, 2048, g_WTfc + bid * 8, fa, As, Ws, tid);
        {
            int fty = tid >> 3, ftx = tid & 7;
            int n = bid * 8 + ftx;
            int b0 = 2 * fty;
            float2 v = unpack2(fa);
            float vb = fc_b[n];
            float p0 = v.x + vb, p1 = v.y + vb;
            size_t o0 = ((size_t)b0 * SS + t) * 1024 + n;
            size_t o1 = ((size_t)(b0 + 1) * SS + t) * 1024 + n;
            out[o0] = p0;
            out[o1] = p1;
            int mk = g_mask[t];
            g_dA[cur ^ 1][b0 * 2048 + n]       = mk ? target[o0] : p0;
            g_dA[cur ^ 1][(b0 + 1) * 2048 + n] = mk ? target[o1] : p1;
        }
        grid_sync();   // inp written before next gate GEMM
        cur ^= 1;
    }
}

// ============ standalone pre-GEMM: gatesX = x @ (packed Wih^T) ============
// tile 64m x 64n, 256 threads, per-thread 4 m-pairs x 2 n
__global__ __launch_bounds__(256)
void gemm256(const float* __restrict__ A, const float* __restrict__ W,
             float* __restrict__ C)
{
    __shared__ float As[32 * 64];
    __shared__ float Ws[32 * 64];

    const int tid = threadIdx.x;
    const int nBase = blockIdx.x * 64;
    const int mBase = blockIdx.y * 64;
    const int ty = tid >> 5, tx = tid & 31;

    ull acc[4][2];
#pragma unroll
    for (int p = 0; p < 4; ++p) { acc[p][0] = 0ull; acc[p][1] = 0ull; }

    const float* Ablk = A + (size_t)mBase * 1024;
    float4 pa[2], pw[2];
    loadA(Ablk, 1024, 0, pa, tid);
#pragma unroll
    for (int i = 0; i < 2; ++i) {
        int idx = tid + i * 256;
        pw[i] = *(const float4*)(W + (size_t)(idx >> 4) * 4096 + nBase + (idx & 15) * 4);
    }

    for (int kt = 0; kt < 1024; kt += 32) {
        storeA(As, pa, tid);
#pragma unroll
        for (int i = 0; i < 2; ++i) {
            int idx = tid + i * 256;
            *(float4*)&Ws[(idx >> 4) * 64 + (idx & 15) * 4] = pw[i];
        }
        __syncthreads();
        if (kt + 32 < 1024) {
            loadA(Ablk, 1024, kt + 32, pa, tid);
#pragma unroll
            for (int i = 0; i < 2; ++i) {
                int idx = tid + i * 256;
                pw[i] = *(const float4*)(W + (size_t)(kt + 32 + (idx >> 4)) * 4096 + nBase + (idx & 15) * 4);
            }
        }
#pragma unroll
        for (int kk = 0; kk < 32; ++kk) {
            int sw = kk >> 2;
            ulonglong2 aa = *(const ulonglong2*)&As[kk * 64 + (((2 * ty)     ^ sw) << 2)];
            ulonglong2 ab = *(const ulonglong2*)&As[kk * 64 + ((((2 * ty) | 1) ^ sw) << 2)];
            float2 wv = *(const float2*)&Ws[kk * 64 + 2 * tx];
            ull w0 = dup2(wv.x), w1 = dup2(wv.y);
            fma2(acc[0][0], aa.x, w0); fma2(acc[0][1], aa.x, w1);
            fma2(acc[1][0], aa.y, w0); fma2(acc[1][1], aa.y, w1);
            fma2(acc[2][0], ab.x, w0); fma2(acc[2][1], ab.x, w1);
            fma2(acc[3][0], ab.y, w0); fma2(acc[3][1], ab.y, w1);
        }
        __syncthreads();
    }
#pragma unroll
    for (int p = 0; p < 4; ++p) {
        float2 c0 = unpack2(acc[p][0]);   // col n0 : rows m0+2p, m0+2p+1
        float2 c1 = unpack2(acc[p][1]);   // col n0+1
        int m = mBase + ty * 8 + 2 * p;
        *(float2*)&C[(size_t)m       * 4096 + nBase + 2 * tx] = make_float2(c0.x, c1.x);
        *(float2*)&C[(size_t)(m + 1) * 4096 + nBase + 2 * tx] = make_float2(c0.y, c1.y);
    }
}

// ---- gate-packed transpose: dst[k*4096 + n'] = src[(n'&3)*1024 + (n'>>2)][k] ----
__global__ void tposeG(float* __restrict__ dst, const float* __restrict__ src)
{
    __shared__ float t[32][33];
    int k0 = blockIdx.x * 32, n0 = blockIdx.y * 32;
#pragma unroll
    for (int i = 0; i < 32; i += 8) {
        int np  = n0 + threadIdx.y + i;
        int row = ((np & 3) << 10) + (np >> 2);
        t[threadIdx.y + i][threadIdx.x] = src[(size_t)row * 1024 + k0 + threadIdx.x];
    }
    __syncthreads();
#pragma unroll
    for (int i = 0; i < 32; i += 8)
        dst[(size_t)(k0 + threadIdx.y + i) * 4096 + n0 + threadIdx.x] = t[threadIdx.x][threadIdx.y + i];
}

// ---- plain transpose (fc): dst[k*1024 + n] = src[n*1024 + k] ----
__global__ void tposeK(float* __restrict__ dst, const float* __restrict__ src)
{
    __shared__ float t[32][33];
    int k0 = blockIdx.x * 32, n0 = blockIdx.y * 32;
#pragma unroll
    for (int i = 0; i < 32; i += 8)
        t[threadIdx.y + i][threadIdx.x] = src[(size_t)(n0 + threadIdx.y + i) * 1024 + k0 + threadIdx.x];
    __syncthreads();
#pragma unroll
    for (int i = 0; i < 32; i += 8)
        dst[(size_t)(k0 + threadIdx.y + i) * 1024 + n0 + threadIdx.x] = t[threadIdx.x][threadIdx.y + i];
}

// ---------------- tf_mask layout probe + decode ----------------
__global__ void mask_decode(const unsigned char* __restrict__ p)
{
    __shared__ int s_odd, s_big;
    int t = threadIdx.x;
    if (t == 0) { s_odd = 0; s_big = 0; }
    __syncthreads();
    unsigned char v = p[t];
    if ((t & 3) && v)  atomicOr(&s_odd, 1);
    if (v > 1)         atomicOr(&s_big, 1);
    __syncthreads();
    int m;
    if (s_big)        m = (((const float*)p)[t] != 0.0f);
    else if (s_odd)   m = (p[t] != 0);
    else              m = (((const int*)p)[t] != 0);
    g_mask[t] = m;
}

// ---------------- init: zero states, pack biases, reset barrier ----------------
__global__ void init_state(const float* __restrict__ enc_b, const float* __restrict__ dec_b)
{
    int i = blockIdx.x * blockDim.x + threadIdx.x;   // 65536
    int b = i >> 10, j = i & 1023;
    g_c[i] = 0.0f;
    g_dA[0][(size_t)b * 2048 + 1024 + j] = 0.0f;
    if (i < 4096) {
        int row = ((i & 3) << 10) + (i >> 2);
        g_bpe[i] = enc_b[row];
        g_bpd[i] = dec_b[row];
    }
    if (i == 0) { g_barCount = 0; g_barGen = 0; }
}

// ---------------- host ----------------
extern "C" void kernel_launch(void* const* d_in, const int* in_sizes, int n_in,
                              void* d_out, int out_size)
{
    (void)in_sizes; (void)n_in; (void)out_size;
    const float* x       = (const float*)d_in[0];
    const float* target  = (const float*)d_in[1];
    const float* enc_Wih = (const float*)d_in[2];
    const float* enc_Whh = (const float*)d_in[3];
    const float* enc_b   = (const float*)d_in[4];
    const float* dec_Wih = (const float*)d_in[5];
    const float* dec_Whh = (const float*)d_in[6];
    const float* dec_b   = (const float*)d_in[7];
    const float* fc_W    = (const float*)d_in[8];
    const float* fc_b    = (const float*)d_in[9];
    const unsigned char* tf_mask = (const unsigned char*)d_in[10];
    float* out = (float*)d_out;

    float *pWTenc, *pWTdec, *pWTfc, *pGatesX;
    cudaGetSymbolAddress((void**)&pWTenc,  g_WTenc);
    cudaGetSymbolAddress((void**)&pWTdec,  g_WTdec);
    cudaGetSymbolAddress((void**)&pWTfc,   g_WTfc);
    cudaGetSymbolAddress((void**)&pGatesX, g_gatesX);

    mask_decode<<<1, 512>>>(tf_mask);

    dim3 tb(32, 8);
    tposeG<<<dim3(32, 128), tb>>>(pWTenc,                       enc_Wih);
    tposeG<<<dim3(32, 128), tb>>>(pWTenc + (size_t)1024 * 4096, enc_Whh);
    tposeG<<<dim3(32, 128), tb>>>(pWTdec,                       dec_Wih);
    tposeG<<<dim3(32, 128), tb>>>(pWTdec + (size_t)1024 * 4096, dec_Whh);
    tposeK<<<dim3(32, 32),  tb>>>(pWTfc,                        fc_W);

    init_state<<<256, 256>>>(enc_b, dec_b);

    // Precompute gatesX[(b*512+t)][n'] = x[b,t,:] @ packed Wih^T  (M=32768, N=4096, K=1024)
    gemm256<<<dim3(64, 512), 256>>>(x, pWTenc, pGatesX);

    // One persistent kernel for the full recurrence (128 co-resident blocks).
    seq2seq_persist<<<NBLK, 256>>>(x, target, fc_b, out);
}

// round 4
// speedup vs baseline: 1.3398x; 1.3398x over previous
#include <cuda_runtime.h>
#include <math.h>

typedef unsigned long long ull;

#define SS 512
#define NBLK 128

// ---------------- device scratch (no allocations allowed) ----------------
__device__ float g_WTenc[2048 * 4096];   // packed [k][n'=4j+g]; rows 0..1023 = Wih, 1024..2047 = Whh
__device__ float g_WTdec[2048 * 4096];   // same packing
__device__ float g_WTfc [1024 * 1024];   // plain [k][n]
__device__ float g_gatesX[(size_t)512 * 4096 * 64]; // [t][n'][b]  (512MB)
__device__ float g_dA[2][64 * 2048];     // ping-pong: [b][0:1024]=inp, [b][1024:2048]=h
__device__ float g_c [64 * 1024];
__device__ float g_bpe[4096], g_bpd[4096];  // gate-packed biases
__device__ int   g_mask[512];
__device__ float g_xchG[NBLK][32][64];   // gate partial exchange: [receiver][col][m]
__device__ float g_xchF[NBLK][8][64];    // fc partial exchange
__device__ int   g_flag[NBLK];
__device__ unsigned g_barL[16];
__device__ unsigned g_barR;
__device__ unsigned g_barGenI;

// ---------------- f32x2 helpers ----------------
__device__ __forceinline__ ull dup2(float v) {
    ull r; unsigned u = __float_as_uint(v);
    asm("mov.b64 %0, {%1, %1};" : "=l"(r) : "r"(u));
    return r;
}
__device__ __forceinline__ void fma2(ull& acc, ull a, ull b) {
    asm("fma.rn.f32x2 %0, %1, %2, %0;" : "+l"(acc) : "l"(a), "l"(b));
}
__device__ __forceinline__ float2 unpack2(ull v) {
    unsigned lo, hi;
    asm("mov.b64 {%0, %1}, %2;" : "=r"(lo), "=r"(hi) : "l"(v));
    return make_float2(__uint_as_float(lo), __uint_as_float(hi));
}
__device__ __forceinline__ float sigf(float x) { return 1.0f / (1.0f + expf(-x)); }

// ---------------- 2-level grid barrier (monotonic counters, no resets) ----------------
__device__ __forceinline__ void grid_sync(unsigned nsync) {
    __syncthreads();
    if (threadIdx.x == 0) {
        __threadfence();
        int l = blockIdx.x >> 3;
        unsigned v = atomicAdd(&g_barL[l], 1u) + 1u;
        if (v == nsync * 8u) {
            unsigned r = atomicAdd(&g_barR, 1u) + 1u;
            if (r == nsync * 16u) atomicExch(&g_barGenI, nsync);
        }
        while (atomicAdd(&g_barGenI, 0u) < nsync) __nanosleep(32);
        __threadfence();
    }
    __syncthreads();
}

// ---------------- pair-wise sync (monotonic flag) ----------------
__device__ __forceinline__ void pair_sync(int bid, int seq) {
    __syncthreads();
    if (threadIdx.x == 0) {
        __threadfence();
        atomicExch(&g_flag[bid], seq);
        while (atomicAdd(&g_flag[bid ^ 1], 0) < seq) __nanosleep(32);
        __threadfence();
    }
    __syncthreads();
}

// ---- A tile staging: 64m x 32k, coalesced loads, XOR-swizzled conflict-free store ----
__device__ __forceinline__ void loadA(const float* __restrict__ A, int lda, int kOff,
                                      float4 pa[2], int tid)
{
    const int k4 = tid & 7;
    const int mA = tid >> 3;
#pragma unroll
    for (int i = 0; i < 2; ++i)
        pa[i] = *(const float4*)(A + (size_t)(mA + 32 * i) * lda + kOff + k4 * 4);
}
__device__ __forceinline__ void storeA(float* As, const float4 pa[2], int tid)
{
    const int k4 = tid & 7;
    const int mA = tid >> 3;
#pragma unroll
    for (int i = 0; i < 2; ++i) {
        int m  = mA + 32 * i;
        int cm = m >> 2;
        const float* e = (const float*)&pa[i];
#pragma unroll
        for (int r = 0; r < 4; ++r) {
            int k = k4 * 4 + r;
            As[k * 64 + ((cm ^ (k >> 2)) << 2) + (m & 3)] = e[r];
        }
    }
}

// ---------------- gate GEMM (persistent): 64m x 64n tile, per-CTA K-slice ----
// 256 threads, per-thread 4 m-pairs x 2 cols = 8 fma2/kk. Result -> sG[m][col].
__device__ __forceinline__ void gemm_pair(const float* __restrict__ A, int lda,
                                          int kOff0, int kLen,
                                          const float* __restrict__ Wp, int ldw,
                                          float* As, float* Ws, float (*sG)[65], int tid)
{
    const int ty = tid >> 5, tx = tid & 31;
    ull acc[4][2];
#pragma unroll
    for (int p = 0; p < 4; ++p) { acc[p][0] = 0ull; acc[p][1] = 0ull; }

    float4 pa[2], pw[2];
    loadA(A, lda, kOff0, pa, tid);
#pragma unroll
    for (int i = 0; i < 2; ++i) {
        int idx = tid + i * 256;
        pw[i] = *(const float4*)(Wp + (size_t)(kOff0 + (idx >> 4)) * ldw + (idx & 15) * 4);
    }

    for (int kt = 0; kt < kLen; kt += 32) {
        storeA(As, pa, tid);
#pragma unroll
        for (int i = 0; i < 2; ++i) {
            int idx = tid + i * 256;
            *(float4*)&Ws[(idx >> 4) * 64 + (idx & 15) * 4] = pw[i];
        }
        __syncthreads();
        if (kt + 32 < kLen) {
            int kOff = kOff0 + kt + 32;
            loadA(A, lda, kOff, pa, tid);
#pragma unroll
            for (int i = 0; i < 2; ++i) {
                int idx = tid + i * 256;
                pw[i] = *(const float4*)(Wp + (size_t)(kOff + (idx >> 4)) * ldw + (idx & 15) * 4);
            }
        }
#pragma unroll
        for (int kk = 0; kk < 32; ++kk) {
            int sw = kk >> 2;
            ulonglong2 aa = *(const ulonglong2*)&As[kk * 64 + (((2 * ty)     ^ sw) << 2)];
            ulonglong2 ab = *(const ulonglong2*)&As[kk * 64 + ((((2 * ty) | 1) ^ sw) << 2)];
            float2 wv = *(const float2*)&Ws[kk * 64 + 2 * tx];
            ull w0 = dup2(wv.x), w1 = dup2(wv.y);
            fma2(acc[0][0], aa.x, w0); fma2(acc[0][1], aa.x, w1);
            fma2(acc[1][0], aa.y, w0); fma2(acc[1][1], aa.y, w1);
            fma2(acc[2][0], ab.x, w0); fma2(acc[2][1], ab.x, w1);
            fma2(acc[3][0], ab.y, w0); fma2(acc[3][1], ab.y, w1);
        }
        __syncthreads();
    }
#pragma unroll
    for (int p = 0; p < 4; ++p) {
        float2 c0 = unpack2(acc[p][0]);
        float2 c1 = unpack2(acc[p][1]);
        int m = ty * 8 + 2 * p;
        sG[m][2 * tx]         = c0.x;
        sG[m][2 * tx + 1]     = c1.x;
        sG[m + 1][2 * tx]     = c0.y;
        sG[m + 1][2 * tx + 1] = c1.y;
    }
    __syncthreads();
}

// ---------------- fc GEMM (persistent): 64m x 16n tile, per-CTA K-slice ----
__device__ __forceinline__ void gemm_fc(const float* __restrict__ A, int lda,
                                        int kOff0, int kLen,
                                        const float* __restrict__ Wp,
                                        float* As, float* Ws, float (*sG)[65], int tid)
{
    const int ty = tid >> 3, tx = tid & 7;     // ty 0..31 -> m-pair, tx -> 2 cols
    ull acc[2]; acc[0] = 0ull; acc[1] = 0ull;

    float4 pa[2], pw;
    loadA(A, lda, kOff0, pa, tid);
    if (tid < 128)
        pw = *(const float4*)(Wp + (size_t)(kOff0 + (tid >> 2)) * 1024 + (tid & 3) * 4);

    for (int kt = 0; kt < kLen; kt += 32) {
        storeA(As, pa, tid);
        if (tid < 128) *(float4*)&Ws[(tid >> 2) * 16 + (tid & 3) * 4] = pw;
        __syncthreads();
        if (kt + 32 < kLen) {
            int kOff = kOff0 + kt + 32;
            loadA(A, lda, kOff, pa, tid);
            if (tid < 128)
                pw = *(const float4*)(Wp + (size_t)(kOff + (tid >> 2)) * 1024 + (tid & 3) * 4);
        }
#pragma unroll
        for (int kk = 0; kk < 32; ++kk) {
            int sw = kk >> 2;
            ull a = *(const ull*)&As[kk * 64 + (((ty >> 1) ^ sw) << 2) + ((2 * ty) & 3)];
            float2 wv = *(const float2*)&Ws[kk * 16 + 2 * tx];
            fma2(acc[0], a, dup2(wv.x));
            fma2(acc[1], a, dup2(wv.y));
        }
        __syncthreads();
    }
    float2 c0 = unpack2(acc[0]);
    float2 c1 = unpack2(acc[1]);
    sG[2 * ty][2 * tx]         = c0.x;
    sG[2 * ty][2 * tx + 1]     = c1.x;
    sG[2 * ty + 1][2 * tx]     = c0.y;
    sG[2 * ty + 1][2 * tx + 1] = c1.y;
    __syncthreads();
}

// ============ the persistent seq2seq kernel ============
__global__ __launch_bounds__(256, 1)
void seq2seq_persist(const float* __restrict__ x, const float* __restrict__ target,
                     const float* __restrict__ fc_b, float* __restrict__ out)
{
    __shared__ float As[32 * 64];
    __shared__ float Ws[32 * 64];
    __shared__ float sG[64][65];

    const int tid = threadIdx.x;
    const int bid = blockIdx.x;
    const int p   = bid >> 1;     // pair index: gate n-tile (64 cols), fc n-tile (16 cols)
    const int kz  = bid & 1;      // K half
    int cur = 0;
    int pseq = 0;
    unsigned nsync = 0;

    const int peerBase  = (kz ^ 1) * 32;   // gate cols we send
    const int ownBase   = kz * 32;         // gate cols we own
    const int peerBaseF = (kz ^ 1) * 8;
    const int ownBaseF  = kz * 8;

    // ---------------- encoder ----------------
    for (int t = 0; t < SS; ++t) {
        gemm_pair(g_dA[cur] + 1024, 2048, kz * 512, 512,
                  g_WTenc + (size_t)1024 * 4096 + p * 64, 4096, As, Ws, sG, tid);
        // send peer its 32 cols
#pragma unroll
        for (int r = 0; r < 8; ++r) {
            int idx = tid + r * 256;
            int m = idx & 63, cc = idx >> 6;
            g_xchG[bid ^ 1][cc][m] = sG[m][peerBase + cc];
        }
        pair_sync(bid, ++pseq);
        // cell for our 8 hidden units x 64 batch
#pragma unroll
        for (int r = 0; r < 2; ++r) {
            int id = tid + 256 * r;
            int b = id & 63, jj = id >> 6;
            int npb = p * 64 + ownBase + 4 * jj;
            int j = npb >> 2;
            const float* gxp = g_gatesX + ((size_t)t * 4096 + npb) * 64 + b;
            float4 bb = *(const float4*)&g_bpe[npb];
            float gi = sG[b][ownBase + 4 * jj + 0] + g_xchG[bid][4 * jj + 0][b] + gxp[0]       + bb.x;
            float gf = sG[b][ownBase + 4 * jj + 1] + g_xchG[bid][4 * jj + 1][b] + gxp[64]      + bb.y;
            float gg = sG[b][ownBase + 4 * jj + 2] + g_xchG[bid][4 * jj + 2][b] + gxp[128]     + bb.z;
            float go = sG[b][ownBase + 4 * jj + 3] + g_xchG[bid][4 * jj + 3][b] + gxp[192]     + bb.w;
            float c  = g_c[b * 1024 + j];
            float cn = sigf(gf) * c + sigf(gi) * tanhf(gg);
            float hn = sigf(go) * tanhf(cn);
            g_c[b * 1024 + j] = cn;
            g_dA[cur ^ 1][b * 2048 + 1024 + j] = hn;
            if (t == SS - 1)
                g_dA[cur ^ 1][b * 2048 + j] = x[((size_t)b * SS + SS - 1) * 1024 + j];
        }
        grid_sync(++nsync);
        cur ^= 1;
    }

    // ---------------- decoder ----------------
    for (int t = 0; t < SS; ++t) {
        gemm_pair(g_dA[cur], 2048, kz * 1024, 1024,
                  g_WTdec + p * 64, 4096, As, Ws, sG, tid);
#pragma unroll
        for (int r = 0; r < 8; ++r) {
            int idx = tid + r * 256;
            int m = idx & 63, cc = idx >> 6;
            g_xchG[bid ^ 1][cc][m] = sG[m][peerBase + cc];
        }
        pair_sync(bid, ++pseq);
#pragma unroll
        for (int r = 0; r < 2; ++r) {
            int id = tid + 256 * r;
            int b = id & 63, jj = id >> 6;
            int npb = p * 64 + ownBase + 4 * jj;
            int j = npb >> 2;
            float4 bb = *(const float4*)&g_bpd[npb];
            float gi = sG[b][ownBase + 4 * jj + 0] + g_xchG[bid][4 * jj + 0][b] + bb.x;
            float gf = sG[b][ownBase + 4 * jj + 1] + g_xchG[bid][4 * jj + 1][b] + bb.y;
            float gg = sG[b][ownBase + 4 * jj + 2] + g_xchG[bid][4 * jj + 2][b] + bb.z;
            float go = sG[b][ownBase + 4 * jj + 3] + g_xchG[bid][4 * jj + 3][b] + bb.w;
            float c  = g_c[b * 1024 + j];
            float cn = sigf(gf) * c + sigf(gi) * tanhf(gg);
            float hn = sigf(go) * tanhf(cn);
            g_c[b * 1024 + j] = cn;
            g_dA[cur ^ 1][b * 2048 + 1024 + j] = hn;
        }
        grid_sync(++nsync);   // all h visible before fc reads full K

        gemm_fc(g_dA[cur ^ 1] + 1024, 2048, kz * 512, 512,
                g_WTfc + p * 16, As, Ws, sG, tid);
#pragma unroll
        for (int r = 0; r < 2; ++r) {
            int idx = tid + r * 256;
            int m = idx & 63, cc = idx >> 6;
            g_xchF[bid ^ 1][cc][m] = sG[m][peerBaseF + cc];
        }
        pair_sync(bid, ++pseq);
#pragma unroll
        for (int r = 0; r < 2; ++r) {
            int id = tid + 256 * r;
            int b = id & 63, cc = id >> 6;
            int n = p * 16 + ownBaseF + cc;
            float v = sG[b][ownBaseF + cc] + g_xchF[bid][cc][b] + fc_b[n];
            size_t oidx = ((size_t)b * SS + t) * 1024 + n;
            out[oidx] = v;
            g_dA[cur ^ 1][b * 2048 + n] = g_mask[t] ? target[oidx] : v;
        }
        grid_sync(++nsync);   // inputs visible before next gate GEMM
        cur ^= 1;
    }
}

// ============ pre-GEMM: gatesX[t][n'][b] = x[b,t,:] @ packed Wih^T ============
// blockIdx.y = t; tile rows = 64 b's; blockIdx.x = n-tile (64 cols).
__global__ __launch_bounds__(256)
void gemm256(const float* __restrict__ x, const float* __restrict__ W,
             float* __restrict__ C)
{
    __shared__ float As[32 * 64];
    __shared__ float Ws[32 * 64];
    __shared__ float sG[64][65];

    const int tid = threadIdx.x;
    const int nBase = blockIdx.x * 64;
    const int tt    = blockIdx.y;
    const int ty = tid >> 5, tx = tid & 31;
    const int k4 = tid & 7, mA = tid >> 3;

    ull acc[4][2];
#pragma unroll
    for (int p = 0; p < 4; ++p) { acc[p][0] = 0ull; acc[p][1] = 0ull; }

    // row pointers: row m = batch b, data at x[(b*512 + tt)*1024]
    const float* rp0 = x + ((size_t)mA        * SS + tt) * 1024;
    const float* rp1 = x + ((size_t)(mA + 32) * SS + tt) * 1024;

    float4 pa[2], pw[2];
    pa[0] = *(const float4*)(rp0 + k4 * 4);
    pa[1] = *(const float4*)(rp1 + k4 * 4);
#pragma unroll
    for (int i = 0; i < 2; ++i) {
        int idx = tid + i * 256;
        pw[i] = *(const float4*)(W + (size_t)(idx >> 4) * 4096 + nBase + (idx & 15) * 4);
    }

    for (int kt = 0; kt < 1024; kt += 32) {
        storeA(As, pa, tid);
#pragma unroll
        for (int i = 0; i < 2; ++i) {
            int idx = tid + i * 256;
            *(float4*)&Ws[(idx >> 4) * 64 + (idx & 15) * 4] = pw[i];
        }
        __syncthreads();
        if (kt + 32 < 1024) {
            pa[0] = *(const float4*)(rp0 + kt + 32 + k4 * 4);
            pa[1] = *(const float4*)(rp1 + kt + 32 + k4 * 4);
#pragma unroll
            for (int i = 0; i < 2; ++i) {
                int idx = tid + i * 256;
                pw[i] = *(const float4*)(W + (size_t)(kt + 32 + (idx >> 4)) * 4096 + nBase + (idx & 15) * 4);
            }
        }
#pragma unroll
        for (int kk = 0; kk < 32; ++kk) {
            int sw = kk >> 2;
            ulonglong2 aa = *(const ulonglong2*)&As[kk * 64 + (((2 * ty)     ^ sw) << 2)];
            ulonglong2 ab = *(const ulonglong2*)&As[kk * 64 + ((((2 * ty) | 1) ^ sw) << 2)];
            float2 wv = *(const float2*)&Ws[kk * 64 + 2 * tx];
            ull w0 = dup2(wv.x), w1 = dup2(wv.y);
            fma2(acc[0][0], aa.x, w0); fma2(acc[0][1], aa.x, w1);
            fma2(acc[1][0], aa.y, w0); fma2(acc[1][1], aa.y, w1);
            fma2(acc[2][0], ab.x, w0); fma2(acc[2][1], ab.x, w1);
            fma2(acc[3][0], ab.y, w0); fma2(acc[3][1], ab.y, w1);
        }
        __syncthreads();
    }
    // stage to smem as sG[b][col], then coalesced transpose-store
#pragma unroll
    for (int p = 0; p < 4; ++p) {
        float2 c0 = unpack2(acc[p][0]);
        float2 c1 = unpack2(acc[p][1]);
        int m = ty * 8 + 2 * p;
        sG[m][2 * tx]         = c0.x;
        sG[m][2 * tx + 1]     = c1.x;
        sG[m + 1][2 * tx]     = c0.y;
        sG[m + 1][2 * tx + 1] = c1.y;
    }
    __syncthreads();
    // write C[((t*4096)+nBase+col)*64 + b]: 64 cols x 64 b, float4 over b
#pragma unroll
    for (int rr = 0; rr < 4; ++rr) {
        int col = rr * 16 + (tid >> 4);
        int b4  = (tid & 15) * 4;
        float4 v = make_float4(sG[b4][col], sG[b4 + 1][col], sG[b4 + 2][col], sG[b4 + 3][col]);
        *(float4*)&C[((size_t)tt * 4096 + nBase + col) * 64 + b4] = v;
    }
}

// ---- gate-packed transpose: dst[k*4096 + n'] = src[(n'&3)*1024 + (n'>>2)][k] ----
__global__ void tposeG(float* __restrict__ dst, const float* __restrict__ src)
{
    __shared__ float t[32][33];
    int k0 = blockIdx.x * 32, n0 = blockIdx.y * 32;
#pragma unroll
    for (int i = 0; i < 32; i += 8) {
        int np  = n0 + threadIdx.y + i;
        int row = ((np & 3) << 10) + (np >> 2);
        t[threadIdx.y + i][threadIdx.x] = src[(size_t)row * 1024 + k0 + threadIdx.x];
    }
    __syncthreads();
#pragma unroll
    for (int i = 0; i < 32; i += 8)
        dst[(size_t)(k0 + threadIdx.y + i) * 4096 + n0 + threadIdx.x] = t[threadIdx.x][threadIdx.y + i];
}

// ---- plain transpose (fc): dst[k*1024 + n] = src[n*1024 + k] ----
__global__ void tposeK(float* __restrict__ dst, const float* __restrict__ src)
{
    __shared__ float t[32][33];
    int k0 = blockIdx.x * 32, n0 = blockIdx.y * 32;
#pragma unroll
    for (int i = 0; i < 32; i += 8)
        t[threadIdx.y + i][threadIdx.x] = src[(size_t)(n0 + threadIdx.y + i) * 1024 + k0 + threadIdx.x];
    __syncthreads();
#pragma unroll
    for (int i = 0; i < 32; i += 8)
        dst[(size_t)(k0 + threadIdx.y + i) * 1024 + n0 + threadIdx.x] = t[threadIdx.x][threadIdx.y + i];
}

// ---------------- tf_mask layout probe + decode ----------------
__global__ void mask_decode(const unsigned char* __restrict__ p)
{
    __shared__ int s_odd, s_big;
    int t = threadIdx.x;
    if (t == 0) { s_odd = 0; s_big = 0; }
    __syncthreads();
    unsigned char v = p[t];
    if ((t & 3) && v)  atomicOr(&s_odd, 1);
    if (v > 1)         atomicOr(&s_big, 1);
    __syncthreads();
    int m;
    if (s_big)        m = (((const float*)p)[t] != 0.0f);
    else if (s_odd)   m = (p[t] != 0);
    else              m = (((const int*)p)[t] != 0);
    g_mask[t] = m;
}

// ---------------- init: zero states, pack biases, reset sync state ----------------
__global__ void init_state(const float* __restrict__ enc_b, const float* __restrict__ dec_b)
{
    int i = blockIdx.x * blockDim.x + threadIdx.x;   // 65536
    int b = i >> 10, j = i & 1023;
    g_c[i] = 0.0f;
    g_dA[0][(size_t)b * 2048 + 1024 + j] = 0.0f;
    if (i < 4096) {
        int row = ((i & 3) << 10) + (i >> 2);
        g_bpe[i] = enc_b[row];
        g_bpd[i] = dec_b[row];
    }
    if (i < NBLK) g_flag[i] = 0;
    if (i < 16)   g_barL[i] = 0u;
    if (i == 0) { g_barR = 0u; g_barGenI = 0u; }
}

// ---------------- host ----------------
extern "C" void kernel_launch(void* const* d_in, const int* in_sizes, int n_in,
                              void* d_out, int out_size)
{
    (void)in_sizes; (void)n_in; (void)out_size;
    const float* x       = (const float*)d_in[0];
    const float* target  = (const float*)d_in[1];
    const float* enc_Wih = (const float*)d_in[2];
    const float* enc_Whh = (const float*)d_in[3];
    const float* enc_b   = (const float*)d_in[4];
    const float* dec_Wih = (const float*)d_in[5];
    const float* dec_Whh = (const float*)d_in[6];
    const float* dec_b   = (const float*)d_in[7];
    const float* fc_W    = (const float*)d_in[8];
    const float* fc_b    = (const float*)d_in[9];
    const unsigned char* tf_mask = (const unsigned char*)d_in[10];
    float* out = (float*)d_out;

    float *pWTenc, *pWTdec, *pWTfc, *pGatesX;
    cudaGetSymbolAddress((void**)&pWTenc,  g_WTenc);
    cudaGetSymbolAddress((void**)&pWTdec,  g_WTdec);
    cudaGetSymbolAddress((void**)&pWTfc,   g_WTfc);
    cudaGetSymbolAddress((void**)&pGatesX, g_gatesX);

    mask_decode<<<1, 512>>>(tf_mask);

    dim3 tb(32, 8);
    tposeG<<<dim3(32, 128), tb>>>(pWTenc,                       enc_Wih);
    tposeG<<<dim3(32, 128), tb>>>(pWTenc + (size_t)1024 * 4096, enc_Whh);
    tposeG<<<dim3(32, 128), tb>>>(pWTdec,                       dec_Wih);
    tposeG<<<dim3(32, 128), tb>>>(pWTdec + (size_t)1024 * 4096, dec_Whh);
    tposeK<<<dim3(32, 32),  tb>>>(pWTfc,                        fc_W);

    init_state<<<256, 256>>>(enc_b, dec_b);

    // Precompute gatesX[t][n'][b]  (M=64 b's per t-tile, N=4096, K=1024)
    gemm256<<<dim3(64, 512), 256>>>(x, pWTenc, pGatesX);

    // One persistent kernel for the full recurrence (128 co-resident blocks).
    seq2seq_persist<<<NBLK, 256>>>(x, target, fc_b, out);
}

// round 5
// speedup vs baseline: 1.3944x; 1.0407x over previous
#include <cuda_runtime.h>
#include <math.h>
#include <stdint.h>

typedef unsigned long long ull;

#define SS 512
#define NBLK 128

// ---------------- device scratch (no allocations allowed) ----------------
__device__ float g_WTenc[2048 * 4096];   // packed [k][n'=4j+g]; rows 0..1023 = Wih, 1024..2047 = Whh
__device__ float g_WTdec[2048 * 4096];   // same packing
__device__ float g_WTfc [1024 * 1024];   // plain [k][n]
__device__ float g_gatesX[(size_t)512 * 4096 * 64]; // [t][n'][b]  (512MB)
__device__ float g_dA[2][64 * 2048];     // ping-pong: [b][0:1024]=inp, [b][1024:2048]=h
__device__ float g_c [64 * 1024];
__device__ float g_bpe[4096], g_bpd[4096];  // gate-packed biases
__device__ int   g_mask[512];
__device__ unsigned          g_barL[16];
__device__ unsigned          g_barR;
__device__ volatile unsigned g_barGen;

// ---------------- f32x2 / PTX helpers ----------------
__device__ __forceinline__ ull dup2(float v) {
    ull r; unsigned u = __float_as_uint(v);
    asm("mov.b64 %0, {%1, %1};" : "=l"(r) : "r"(u));
    return r;
}
__device__ __forceinline__ void fma2(ull& acc, ull a, ull b) {
    asm("fma.rn.f32x2 %0, %1, %2, %0;" : "+l"(acc) : "l"(a), "l"(b));
}
__device__ __forceinline__ float2 unpack2(ull v) {
    unsigned lo, hi;
    asm("mov.b64 {%0, %1}, %2;" : "=r"(lo), "=r"(hi) : "l"(v));
    return make_float2(__uint_as_float(lo), __uint_as_float(hi));
}
__device__ __forceinline__ float sigf(float x) { return 1.0f / (1.0f + expf(-x)); }

__device__ __forceinline__ uint32_t smem_u32(const void* p) {
    uint32_t a;
    asm("{ .reg .u64 t; cvta.to.shared.u64 t, %1; cvt.u32.u64 %0, t; }" : "=r"(a) : "l"(p));
    return a;
}
__device__ __forceinline__ uint32_t mapa_rank(uint32_t addr, uint32_t rank) {
    uint32_t r;
    asm("mapa.shared::cluster.u32 %0, %1, %2;" : "=r"(r) : "r"(addr), "r"(rank));
    return r;
}
__device__ __forceinline__ void stc64(uint32_t addr, ull v) {
    asm volatile("st.shared::cluster.b64 [%0], %1;" :: "r"(addr), "l"(v) : "memory");
}
#define CARRIVE() asm volatile("barrier.cluster.arrive.aligned;" ::: "memory")
#define CWAIT()   asm volatile("barrier.cluster.wait.aligned;"   ::: "memory")

// ---------------- grid barrier: tree arrival + volatile-load poll ----------------
__device__ __forceinline__ void grid_sync(unsigned n) {
    __syncthreads();
    if (threadIdx.x == 0) {
        __threadfence();
        int l = blockIdx.x >> 3;                       // 16 leaves x 8 CTAs
        if (atomicAdd(&g_barL[l], 1u) + 1u == n * 8u) {
            if (atomicAdd(&g_barR, 1u) + 1u == n * 16u) {
                g_barGen = n;                          // volatile release store
            }
        }
        while (g_barGen < n) { }                       // plain volatile load spin
        __threadfence();
    }
    __syncthreads();
}

// ---- A tile staging: 64m x 32k, coalesced loads, XOR-swizzled conflict-free store ----
__device__ __forceinline__ void loadA(const float* __restrict__ A, int lda, int kOff,
                                      float4 pa[2], int tid)
{
    const int k4 = tid & 7;
    const int mA = tid >> 3;
#pragma unroll
    for (int i = 0; i < 2; ++i)
        pa[i] = *(const float4*)(A + (size_t)(mA + 32 * i) * lda + kOff + k4 * 4);
}
__device__ __forceinline__ void storeA(float* As, const float4 pa[2], int tid)
{
    const int k4 = tid & 7;
    const int mA = tid >> 3;
#pragma unroll
    for (int i = 0; i < 2; ++i) {
        int m  = mA + 32 * i;
        int cm = m >> 2;
        const float* e = (const float*)&pa[i];
#pragma unroll
        for (int r = 0; r < 4; ++r) {
            int k = k4 * 4 + r;
            As[k * 64 + ((cm ^ (k >> 2)) << 2) + (m & 3)] = e[r];
        }
    }
}

// ---------------- gate GEMM: 64m x 64n tile, per-CTA K-slice, acc in regs ----------------
__device__ __forceinline__ void gemm_gate(const float* __restrict__ A, int lda,
                                          int kOff0, int kLen,
                                          const float* __restrict__ Wp, int ldw,
                                          float* As, float* Ws, ull acc[4][2], int tid)
{
    const int ty = tid >> 5, tx = tid & 31;
#pragma unroll
    for (int p = 0; p < 4; ++p) { acc[p][0] = 0ull; acc[p][1] = 0ull; }

    float4 pa[2], pw[2];
    loadA(A, lda, kOff0, pa, tid);
#pragma unroll
    for (int i = 0; i < 2; ++i) {
        int idx = tid + i * 256;
        pw[i] = *(const float4*)(Wp + (size_t)(kOff0 + (idx >> 4)) * ldw + (idx & 15) * 4);
    }

    for (int kt = 0; kt < kLen; kt += 32) {
        storeA(As, pa, tid);
#pragma unroll
        for (int i = 0; i < 2; ++i) {
            int idx = tid + i * 256;
            *(float4*)&Ws[(idx >> 4) * 64 + (idx & 15) * 4] = pw[i];
        }
        __syncthreads();
        if (kt + 32 < kLen) {
            int kOff = kOff0 + kt + 32;
            loadA(A, lda, kOff, pa, tid);
#pragma unroll
            for (int i = 0; i < 2; ++i) {
                int idx = tid + i * 256;
                pw[i] = *(const float4*)(Wp + (size_t)(kOff + (idx >> 4)) * ldw + (idx & 15) * 4);
            }
        }
#pragma unroll
        for (int kk = 0; kk < 32; ++kk) {
            int sw = kk >> 2;
            ulonglong2 aa = *(const ulonglong2*)&As[kk * 64 + (((2 * ty)     ^ sw) << 2)];
            ulonglong2 ab = *(const ulonglong2*)&As[kk * 64 + ((((2 * ty) | 1) ^ sw) << 2)];
            float2 wv = *(const float2*)&Ws[kk * 64 + 2 * tx];
            ull w0 = dup2(wv.x), w1 = dup2(wv.y);
            fma2(acc[0][0], aa.x, w0); fma2(acc[0][1], aa.x, w1);
            fma2(acc[1][0], aa.y, w0); fma2(acc[1][1], aa.y, w1);
            fma2(acc[2][0], ab.x, w0); fma2(acc[2][1], ab.x, w1);
            fma2(acc[3][0], ab.y, w0); fma2(acc[3][1], ab.y, w1);
        }
        __syncthreads();
    }
}

// ---------------- fc GEMM: 64m x 16n tile, per-CTA K-slice ----------------
__device__ __forceinline__ void gemm_fc(const float* __restrict__ A, int lda,
                                        int kOff0, int kLen,
                                        const float* __restrict__ Wp,
                                        float* As, float* Ws, ull acc[2], int tid)
{
    const int ty = tid >> 3, tx = tid & 7;
    acc[0] = 0ull; acc[1] = 0ull;

    float4 pa[2], pw;
    loadA(A, lda, kOff0, pa, tid);
    if (tid < 128)
        pw = *(const float4*)(Wp + (size_t)(kOff0 + (tid >> 2)) * 1024 + (tid & 3) * 4);

    for (int kt = 0; kt < kLen; kt += 32) {
        storeA(As, pa, tid);
        if (tid < 128) *(float4*)&Ws[(tid >> 2) * 16 + (tid & 3) * 4] = pw;
        __syncthreads();
        if (kt + 32 < kLen) {
            int kOff = kOff0 + kt + 32;
            loadA(A, lda, kOff, pa, tid);
            if (tid < 128)
                pw = *(const float4*)(Wp + (size_t)(kOff + (tid >> 2)) * 1024 + (tid & 3) * 4);
        }
#pragma unroll
        for (int kk = 0; kk < 32; ++kk) {
            int sw = kk >> 2;
            ull a = *(const ull*)&As[kk * 64 + (((ty >> 1) ^ sw) << 2) + ((2 * ty) & 3)];
            float2 wv = *(const float2*)&Ws[kk * 16 + 2 * tx];
            fma2(acc[0], a, dup2(wv.x));
            fma2(acc[1], a, dup2(wv.y));
        }
        __syncthreads();
    }
}

// ============ the persistent seq2seq kernel (64 clusters of 2) ============
__global__ __launch_bounds__(256, 1) __cluster_dims__(2, 1, 1)
void seq2seq_persist(const float* __restrict__ x, const float* __restrict__ target,
                     const float* __restrict__ fc_b, float* __restrict__ out)
{
    __shared__ float As[32 * 64];
    __shared__ float Ws[32 * 64];
    __shared__ float sOwn [32][66];   // own K-half partial, [col][m]
    __shared__ float sRecv[32][66];   // peer K-half partial, written via DSMEM

    const int tid = threadIdx.x;
    const int bid = blockIdx.x;
    const int p   = bid >> 1;     // pair: gate n-tile (64 cols), fc n-tile (16 cols)
    const int kz  = bid & 1;      // K half == cluster rank

    const uint32_t sOwnA  = smem_u32(sOwn);
    const uint32_t sRecvA = smem_u32(sRecv);
    const uint32_t peerRecvA = mapa_rank(sRecvA, (uint32_t)(kz ^ 1));

    int cur = 0;
    unsigned nsync = 0;

    // ---------------- encoder ----------------
    for (int t = 0; t < SS; ++t) {
        ull acc[4][2];
        gemm_gate(g_dA[cur] + 1024, 2048, kz * 512, 512,
                  g_WTenc + (size_t)1024 * 4096 + p * 64, 4096, As, Ws, acc, tid);
        // epilogue: own half -> sOwn, peer half -> peer's sRecv (identical layout)
        {
            const int ty = tid >> 5, tx = tid & 31;
            const int txl = tx & 15;
            const bool own = ((tx >> 4) == kz);
            const uint32_t base = own ? sOwnA : peerRecvA;
#pragma unroll
            for (int q = 0; q < 4; ++q) {
                int m = ty * 8 + 2 * q;
                stc64(base + (uint32_t)(((2 * txl)     * 66 + m) * 4), acc[q][0]);
                stc64(base + (uint32_t)(((2 * txl + 1) * 66 + m) * 4), acc[q][1]);
            }
        }
        CARRIVE();
        // prefetch gatesX + bias while waiting for peer partials
        float4 gx[2], bb[2];
#pragma unroll
        for (int r = 0; r < 2; ++r) {
            int id = tid + 256 * r;
            int b = id & 63, jj = id >> 6;
            int npb = p * 64 + kz * 32 + 4 * jj;
            gx[r] = *(const float4*)(g_gatesX + ((size_t)t * 4096 + npb) * 64 + (size_t)b * 4
                                     - (size_t)b * 4 + 0);   // placeholder, fixed below
            bb[r] = *(const float4*)&g_bpe[npb];
        }
        // (gatesX is [t][n'][b]; gather the 4 gate values at stride 64)
        float gxa[2][4];
#pragma unroll
        for (int r = 0; r < 2; ++r) {
            int id = tid + 256 * r;
            int b = id & 63, jj = id >> 6;
            int npb = p * 64 + kz * 32 + 4 * jj;
            const float* gxp = g_gatesX + ((size_t)t * 4096 + npb) * 64 + b;
            gxa[r][0] = gxp[0];   gxa[r][1] = gxp[64];
            gxa[r][2] = gxp[128]; gxa[r][3] = gxp[192];
        }
        CWAIT();
#pragma unroll
        for (int r = 0; r < 2; ++r) {
            int id = tid + 256 * r;
            int b = id & 63, jj = id >> 6;
            int j = p * 16 + kz * 8 + jj;
            float gi = sOwn[4 * jj + 0][b] + sRecv[4 * jj + 0][b] + gxa[r][0] + bb[r].x;
            float gf = sOwn[4 * jj + 1][b] + sRecv[4 * jj + 1][b] + gxa[r][1] + bb[r].y;
            float gg = sOwn[4 * jj + 2][b] + sRecv[4 * jj + 2][b] + gxa[r][2] + bb[r].z;
            float go = sOwn[4 * jj + 3][b] + sRecv[4 * jj + 3][b] + gxa[r][3] + bb[r].w;
            float c  = g_c[b * 1024 + j];
            float cn = sigf(gf) * c + sigf(gi) * tanhf(gg);
            float hn = sigf(go) * tanhf(cn);
            g_c[b * 1024 + j] = cn;
            g_dA[cur ^ 1][b * 2048 + 1024 + j] = hn;
            if (t == SS - 1)   // stage dec_inp0 = x[:, -1, :]
                g_dA[cur ^ 1][b * 2048 + j] = x[((size_t)b * SS + SS - 1) * 1024 + j];
        }
        grid_sync(++nsync);
        cur ^= 1;
    }

    // ---------------- decoder ----------------
    for (int t = 0; t < SS; ++t) {
        ull acc[4][2];
        gemm_gate(g_dA[cur], 2048, kz * 1024, 1024,
                  g_WTdec + p * 64, 4096, As, Ws, acc, tid);
        {
            const int ty = tid >> 5, tx = tid & 31;
            const int txl = tx & 15;
            const bool own = ((tx >> 4) == kz);
            const uint32_t base = own ? sOwnA : peerRecvA;
#pragma unroll
            for (int q = 0; q < 4; ++q) {
                int m = ty * 8 + 2 * q;
                stc64(base + (uint32_t)(((2 * txl)     * 66 + m) * 4), acc[q][0]);
                stc64(base + (uint32_t)(((2 * txl + 1) * 66 + m) * 4), acc[q][1]);
            }
        }
        CARRIVE();
        float4 bb[2];
#pragma unroll
        for (int r = 0; r < 2; ++r) {
            int id = tid + 256 * r;
            int jj = id >> 6;
            bb[r] = *(const float4*)&g_bpd[p * 64 + kz * 32 + 4 * jj];
        }
        CWAIT();
#pragma unroll
        for (int r = 0; r < 2; ++r) {
            int id = tid + 256 * r;
            int b = id & 63, jj = id >> 6;
            int j = p * 16 + kz * 8 + jj;
            float gi = sOwn[4 * jj + 0][b] + sRecv[4 * jj + 0][b] + bb[r].x;
            float gf = sOwn[4 * jj + 1][b] + sRecv[4 * jj + 1][b] + bb[r].y;
            float gg = sOwn[4 * jj + 2][b] + sRecv[4 * jj + 2][b] + bb[r].z;
            float go = sOwn[4 * jj + 3][b] + sRecv[4 * jj + 3][b] + bb[r].w;
            float c  = g_c[b * 1024 + j];
            float cn = sigf(gf) * c + sigf(gi) * tanhf(gg);
            float hn = sigf(go) * tanhf(cn);
            g_c[b * 1024 + j] = cn;
            g_dA[cur ^ 1][b * 2048 + 1024 + j] = hn;
        }
        grid_sync(++nsync);   // all h visible before fc reads full K

        ull fa[2];
        gemm_fc(g_dA[cur ^ 1] + 1024, 2048, kz * 512, 512,
                g_WTfc + p * 16, As, Ws, fa, tid);
        {
            const int fty = tid >> 3, ftx = tid & 7;
            const int txl = ftx & 3;
            const bool own = ((ftx >> 2) == kz);
            const uint32_t base = own ? sOwnA : peerRecvA;
            int m = 2 * fty;
            stc64(base + (uint32_t)(((2 * txl)     * 66 + m) * 4), fa[0]);
            stc64(base + (uint32_t)(((2 * txl + 1) * 66 + m) * 4), fa[1]);
        }
        CARRIVE();
        float vb[2];
#pragma unroll
        for (int r = 0; r < 2; ++r) {
            int id = tid + 256 * r;
            int cc = id >> 6;
            vb[r] = fc_b[p * 16 + kz * 8 + cc];
        }
        int mk = g_mask[t];
        CWAIT();
#pragma unroll
        for (int r = 0; r < 2; ++r) {
            int id = tid + 256 * r;
            int b = id & 63, cc = id >> 6;
            int n = p * 16 + kz * 8 + cc;
            float v = sOwn[cc][b] + sRecv[cc][b] + vb[r];
            size_t oidx = ((size_t)b * SS + t) * 1024 + n;
            out[oidx] = v;
            g_dA[cur ^ 1][b * 2048 + n] = mk ? target[oidx] : v;
        }
        grid_sync(++nsync);   // inputs visible before next gate GEMM
        cur ^= 1;
    }
}

// ============ pre-GEMM: gatesX[t][n'][b] = x[b,t,:] @ packed Wih^T ============
__global__ __launch_bounds__(256)
void gemm256(const float* __restrict__ x, const float* __restrict__ W,
             float* __restrict__ C)
{
    __shared__ float As[32 * 64];
    __shared__ float Ws[32 * 64];
    __shared__ float sG[64][65];

    const int tid = threadIdx.x;
    const int nBase = blockIdx.x * 64;
    const int tt    = blockIdx.y;
    const int ty = tid >> 5, tx = tid & 31;
    const int k4 = tid & 7, mA = tid >> 3;

    ull acc[4][2];
#pragma unroll
    for (int p = 0; p < 4; ++p) { acc[p][0] = 0ull; acc[p][1] = 0ull; }

    const float* rp0 = x + ((size_t)mA        * SS + tt) * 1024;
    const float* rp1 = x + ((size_t)(mA + 32) * SS + tt) * 1024;

    float4 pa[2], pw[2];
    pa[0] = *(const float4*)(rp0 + k4 * 4);
    pa[1] = *(const float4*)(rp1 + k4 * 4);
#pragma unroll
    for (int i = 0; i < 2; ++i) {
        int idx = tid + i * 256;
        pw[i] = *(const float4*)(W + (size_t)(idx >> 4) * 4096 + nBase + (idx & 15) * 4);
    }

    for (int kt = 0; kt < 1024; kt += 32) {
        storeA(As, pa, tid);
#pragma unroll
        for (int i = 0; i < 2; ++i) {
            int idx = tid + i * 256;
            *(float4*)&Ws[(idx >> 4) * 64 + (idx & 15) * 4] = pw[i];
        }
        __syncthreads();
        if (kt + 32 < 1024) {
            pa[0] = *(const float4*)(rp0 + kt + 32 + k4 * 4);
            pa[1] = *(const float4*)(rp1 + kt + 32 + k4 * 4);
#pragma unroll
            for (int i = 0; i < 2; ++i) {
                int idx = tid + i * 256;
                pw[i] = *(const float4*)(W + (size_t)(kt + 32 + (idx >> 4)) * 4096 + nBase + (idx & 15) * 4);
            }
        }
#pragma unroll
        for (int kk = 0; kk < 32; ++kk) {
            int sw = kk >> 2;
            ulonglong2 aa = *(const ulonglong2*)&As[kk * 64 + (((2 * ty)     ^ sw) << 2)];
            ulonglong2 ab = *(const ulonglong2*)&As[kk * 64 + ((((2 * ty) | 1) ^ sw) << 2)];
            float2 wv = *(const float2*)&Ws[kk * 64 + 2 * tx];
            ull w0 = dup2(wv.x), w1 = dup2(wv.y);
            fma2(acc[0][0], aa.x, w0); fma2(acc[0][1], aa.x, w1);
            fma2(acc[1][0], aa.y, w0); fma2(acc[1][1], aa.y, w1);
            fma2(acc[2][0], ab.x, w0); fma2(acc[2][1], ab.x, w1);
            fma2(acc[3][0], ab.y, w0); fma2(acc[3][1], ab.y, w1);
        }
        __syncthreads();
    }
#pragma unroll
    for (int p = 0; p < 4; ++p) {
        float2 c0 = unpack2(acc[p][0]);
        float2 c1 = unpack2(acc[p][1]);
        int m = ty * 8 + 2 * p;
        sG[m][2 * tx]         = c0.x;
        sG[m][2 * tx + 1]     = c1.x;
        sG[m + 1][2 * tx]     = c0.y;
        sG[m + 1][2 * tx + 1] = c1.y;
    }
    __syncthreads();
#pragma unroll
    for (int rr = 0; rr < 4; ++rr) {
        int col = rr * 16 + (tid >> 4);
        int b4  = (tid & 15) * 4;
        float4 v = make_float4(sG[b4][col], sG[b4 + 1][col], sG[b4 + 2][col], sG[b4 + 3][col]);
        *(float4*)&C[((size_t)tt * 4096 + nBase + col) * 64 + b4] = v;
    }
}

// ---- gate-packed transpose: dst[k*4096 + n'] = src[(n'&3)*1024 + (n'>>2)][k] ----
__global__ void tposeG(float* __restrict__ dst, const float* __restrict__ src)
{
    __shared__ float t[32][33];
    int k0 = blockIdx.x * 32, n0 = blockIdx.y * 32;
#pragma unroll
    for (int i = 0; i < 32; i += 8) {
        int np  = n0 + threadIdx.y + i;
        int row = ((np & 3) << 10) + (np >> 2);
        t[threadIdx.y + i][threadIdx.x] = src[(size_t)row * 1024 + k0 + threadIdx.x];
    }
    __syncthreads();
#pragma unroll
    for (int i = 0; i < 32; i += 8)
        dst[(size_t)(k0 + threadIdx.y + i) * 4096 + n0 + threadIdx.x] = t[threadIdx.x][threadIdx.y + i];
}

// ---- plain transpose (fc): dst[k*1024 + n] = src[n*1024 + k] ----
__global__ void tposeK(float* __restrict__ dst, const float* __restrict__ src)
{
    __shared__ float t[32][33];
    int k0 = blockIdx.x * 32, n0 = blockIdx.y * 32;
#pragma unroll
    for (int i = 0; i < 32; i += 8)
        t[threadIdx.y + i][threadIdx.x] = src[(size_t)(n0 + threadIdx.y + i) * 1024 + k0 + threadIdx.x];
    __syncthreads();
#pragma unroll
    for (int i = 0; i < 32; i += 8)
        dst[(size_t)(k0 + threadIdx.y + i) * 1024 + n0 + threadIdx.x] = t[threadIdx.x][threadIdx.y + i];
}

// ---------------- tf_mask layout probe + decode ----------------
__global__ void mask_decode(const unsigned char* __restrict__ p)
{
    __shared__ int s_odd, s_big;
    int t = threadIdx.x;
    if (t == 0) { s_odd = 0; s_big = 0; }
    __syncthreads();
    unsigned char v = p[t];
    if ((t & 3) && v)  atomicOr(&s_odd, 1);
    if (v > 1)         atomicOr(&s_big, 1);
    __syncthreads();
    int m;
    if (s_big)        m = (((const float*)p)[t] != 0.0f);
    else if (s_odd)   m = (p[t] != 0);
    else              m = (((const int*)p)[t] != 0);
    g_mask[t] = m;
}

// ---------------- init: zero states, pack biases, reset sync state ----------------
__global__ void init_state(const float* __restrict__ enc_b, const float* __restrict__ dec_b)
{
    int i = blockIdx.x * blockDim.x + threadIdx.x;   // 65536
    int b = i >> 10, j = i & 1023;
    g_c[i] = 0.0f;
    g_dA[0][(size_t)b * 2048 + 1024 + j] = 0.0f;
    if (i < 4096) {
        int row = ((i & 3) << 10) + (i >> 2);
        g_bpe[i] = enc_b[row];
        g_bpd[i] = dec_b[row];
    }
    if (i < 16) g_barL[i] = 0u;
    if (i == 0) { g_barR = 0u; g_barGen = 0u; }
}

// ---------------- host ----------------
extern "C" void kernel_launch(void* const* d_in, const int* in_sizes, int n_in,
                              void* d_out, int out_size)
{
    (void)in_sizes; (void)n_in; (void)out_size;
    const float* x       = (const float*)d_in[0];
    const float* target  = (const float*)d_in[1];
    const float* enc_Wih = (const float*)d_in[2];
    const float* enc_Whh = (const float*)d_in[3];
    const float* enc_b   = (const float*)d_in[4];
    const float* dec_Wih = (const float*)d_in[5];
    const float* dec_Whh = (const float*)d_in[6];
    const float* dec_b   = (const float*)d_in[7];
    const float* fc_W    = (const float*)d_in[8];
    const float* fc_b    = (const float*)d_in[9];
    const unsigned char* tf_mask = (const unsigned char*)d_in[10];
    float* out = (float*)d_out;

    float *pWTenc, *pWTdec, *pWTfc, *pGatesX;
    cudaGetSymbolAddress((void**)&pWTenc,  g_WTenc);
    cudaGetSymbolAddress((void**)&pWTdec,  g_WTdec);
    cudaGetSymbolAddress((void**)&pWTfc,   g_WTfc);
    cudaGetSymbolAddress((void**)&pGatesX, g_gatesX);

    mask_decode<<<1, 512>>>(tf_mask);

    dim3 tb(32, 8);
    tposeG<<<dim3(32, 128), tb>>>(pWTenc,                       enc_Wih);
    tposeG<<<dim3(32, 128), tb>>>(pWTenc + (size_t)1024 * 4096, enc_Whh);
    tposeG<<<dim3(32, 128), tb>>>(pWTdec,                       dec_Wih);
    tposeG<<<dim3(32, 128), tb>>>(pWTdec + (size_t)1024 * 4096, dec_Whh);
    tposeK<<<dim3(32, 32),  tb>>>(pWTfc,                        fc_W);

    init_state<<<256, 256>>>(enc_b, dec_b);

    // Precompute gatesX[t][n'][b]
    gemm256<<<dim3(64, 512), 256>>>(x, pWTenc, pGatesX);

    // One persistent kernel for the full recurrence (64 clusters of 2 CTAs).
    seq2seq_persist<<<NBLK, 256>>>(x, target, fc_b, out);
}

// round 6
// speedup vs baseline: 1.4219x; 1.0197x over previous
#include <cuda_runtime.h>
#include <math.h>
#include <stdint.h>

typedef unsigned long long ull;

#define SS 512
#define NBLK 128

// ---------------- device scratch (no allocations allowed) ----------------
__device__ float g_WTenc[2048 * 4096];   // packed [k][n'=4j+g]; rows 0..1023 = Wih, 1024..2047 = Whh
__device__ float g_WTdec[2048 * 4096];   // same packing
__device__ float g_WTfc [1024 * 1024];   // plain [k][n]
__device__ float g_gatesX[(size_t)512 * 4096 * 64]; // [t][n'][b]  (512MB)
__device__ float g_dAT[2][2048 * 64];    // ping-pong, [k][b]: k 0..1023 = inp, 1024..2047 = h
__device__ float g_c  [1024 * 64];       // [j][b]
__device__ float g_partG[2][4096 * 64];  // gate partials [kz][n'][b]
__device__ float g_partF[2][1024 * 64];  // fc partials   [kz][n][b]
__device__ float g_bpe[4096], g_bpd[4096];
__device__ int   g_mask[512];
__device__ unsigned           g_barCount;
__device__ volatile unsigned  g_barGen;

// ---------------- f32x2 helpers ----------------
__device__ __forceinline__ ull dup2(float v) {
    ull r; unsigned u = __float_as_uint(v);
    asm("mov.b64 %0, {%1, %1};" : "=l"(r) : "r"(u));
    return r;
}
__device__ __forceinline__ void fma2(ull& acc, ull a, ull b) {
    asm("fma.rn.f32x2 %0, %1, %2, %0;" : "+l"(acc) : "l"(a), "l"(b));
}
__device__ __forceinline__ float2 unpack2(ull v) {
    unsigned lo, hi;
    asm("mov.b64 {%0, %1}, %2;" : "=r"(lo), "=r"(hi) : "l"(v));
    return make_float2(__uint_as_float(lo), __uint_as_float(hi));
}
__device__ __forceinline__ float sigf(float x) { return 1.0f / (1.0f + expf(-x)); }

// ---------------- grid barrier (R2-proven: single counter + volatile gen) ----------------
__device__ __forceinline__ void grid_sync() {
    __syncthreads();
    if (threadIdx.x == 0) {
        __threadfence();
        unsigned gen = g_barGen;
        if (atomicAdd(&g_barCount, 1u) == NBLK - 1) {
            g_barCount = 0;
            __threadfence();
            g_barGen = gen + 1;
        } else {
            while (g_barGen == gen) { }
        }
        __threadfence();
    }
    __syncthreads();
}

// ============ gate GEMM: A[k][64b] (direct copy, no transpose), tile 64b x 64n ============
// 256 threads, per-thread 4 b-pairs x 2 cols = 8 fma2/kk. Result staged in sG[col][b].
__device__ __forceinline__ void gemm_gate(const float* __restrict__ A,      // [k][64]
                                          const float* __restrict__ Wp,    // + col offset, ldw 4096
                                          int kLen,
                                          float* As, float* Ws, float (*sG)[66], int tid)
{
    const int ty = tid >> 5, tx = tid & 31;
    ull acc[4][2];
#pragma unroll
    for (int q = 0; q < 4; ++q) { acc[q][0] = 0ull; acc[q][1] = 0ull; }

    float4 pa[2], pw[2];
#pragma unroll
    for (int i = 0; i < 2; ++i) {
        int idx = tid + i * 256;
        pa[i] = *(const float4*)(A + (size_t)(idx >> 4) * 64 + (idx & 15) * 4);
        pw[i] = *(const float4*)(Wp + (size_t)(idx >> 4) * 4096 + (idx & 15) * 4);
    }

    for (int kt = 0; kt < kLen; kt += 32) {
#pragma unroll
        for (int i = 0; i < 2; ++i) {
            int idx = tid + i * 256;
            *(float4*)&As[(idx >> 4) * 64 + (idx & 15) * 4] = pa[i];
            *(float4*)&Ws[(idx >> 4) * 64 + (idx & 15) * 4] = pw[i];
        }
        __syncthreads();
        if (kt + 32 < kLen) {
            int kOff = kt + 32;
#pragma unroll
            for (int i = 0; i < 2; ++i) {
                int idx = tid + i * 256;
                pa[i] = *(const float4*)(A + (size_t)(kOff + (idx >> 4)) * 64 + (idx & 15) * 4);
                pw[i] = *(const float4*)(Wp + (size_t)(kOff + (idx >> 4)) * 4096 + (idx & 15) * 4);
            }
        }
#pragma unroll
        for (int kk = 0; kk < 32; ++kk) {
            ulonglong2 aa = *(const ulonglong2*)&As[kk * 64 + 8 * ty];       // b-pairs, broadcast
            ulonglong2 ab = *(const ulonglong2*)&As[kk * 64 + 8 * ty + 4];
            float2 wv = *(const float2*)&Ws[kk * 64 + 2 * tx];
            ull w0 = dup2(wv.x), w1 = dup2(wv.y);
            fma2(acc[0][0], aa.x, w0); fma2(acc[0][1], aa.x, w1);
            fma2(acc[1][0], aa.y, w0); fma2(acc[1][1], aa.y, w1);
            fma2(acc[2][0], ab.x, w0); fma2(acc[2][1], ab.x, w1);
            fma2(acc[3][0], ab.y, w0); fma2(acc[3][1], ab.y, w1);
        }
        __syncthreads();
    }
    // stage sG[col][b]
#pragma unroll
    for (int q = 0; q < 4; ++q) {
        int b = 8 * ty + 2 * q;
        *(ull*)&sG[2 * tx][b]     = acc[q][0];
        *(ull*)&sG[2 * tx + 1][b] = acc[q][1];
    }
    __syncthreads();
}

// ============ fc GEMM: tile 64b x 16n, K-slice; result in sG[col][b] ============
__device__ __forceinline__ void gemm_fc(const float* __restrict__ A,       // [k][64]
                                        const float* __restrict__ Wp,     // + col offset, ldw 1024
                                        int kLen,
                                        float* As, float* Ws, float (*sG)[66], int tid)
{
    const int ty = tid >> 3, tx = tid & 7;    // ty: b-pair, tx: 2 cols
    ull acc[2]; acc[0] = 0ull; acc[1] = 0ull;

    float4 pa[2], pw;
#pragma unroll
    for (int i = 0; i < 2; ++i) {
        int idx = tid + i * 256;
        pa[i] = *(const float4*)(A + (size_t)(idx >> 4) * 64 + (idx & 15) * 4);
    }
    if (tid < 128)
        pw = *(const float4*)(Wp + (size_t)(tid >> 2) * 1024 + (tid & 3) * 4);

    for (int kt = 0; kt < kLen; kt += 32) {
#pragma unroll
        for (int i = 0; i < 2; ++i) {
            int idx = tid + i * 256;
            *(float4*)&As[(idx >> 4) * 64 + (idx & 15) * 4] = pa[i];
        }
        if (tid < 128) *(float4*)&Ws[(tid >> 2) * 16 + (tid & 3) * 4] = pw;
        __syncthreads();
        if (kt + 32 < kLen) {
            int kOff = kt + 32;
#pragma unroll
            for (int i = 0; i < 2; ++i) {
                int idx = tid + i * 256;
                pa[i] = *(const float4*)(A + (size_t)(kOff + (idx >> 4)) * 64 + (idx & 15) * 4);
            }
            if (tid < 128)
                pw = *(const float4*)(Wp + (size_t)(kOff + (tid >> 2)) * 1024 + (tid & 3) * 4);
        }
#pragma unroll
        for (int kk = 0; kk < 32; ++kk) {
            ull a = *(const ull*)&As[kk * 64 + 2 * ty];
            float2 wv = *(const float2*)&Ws[kk * 16 + 2 * tx];
            fma2(acc[0], a, dup2(wv.x));
            fma2(acc[1], a, dup2(wv.y));
        }
        __syncthreads();
    }
    *(ull*)&sG[2 * tx][2 * ty]     = acc[0];
    *(ull*)&sG[2 * tx + 1][2 * ty] = acc[1];
    __syncthreads();
}

// ============ the persistent seq2seq kernel ============
__global__ __launch_bounds__(256, 1)
void seq2seq_persist(const float* __restrict__ x, const float* __restrict__ target,
                     const float* __restrict__ fc_b, float* __restrict__ out)
{
    __shared__ __align__(16) float As[32 * 64];
    __shared__ __align__(16) float Ws[32 * 64];
    __shared__ __align__(16) float sG[64][66];

    const int tid = threadIdx.x;
    const int bid = blockIdx.x;
    const int p   = bid >> 1;     // n-tile: gate 64 cols / fc 16 cols
    const int kz  = bid & 1;      // K half
    int cur = 0;

    // ---------------- encoder ----------------
    for (int t = 0; t < SS; ++t) {
        gemm_gate(g_dAT[cur] + (size_t)(1024 + kz * 512) * 64,
                  g_WTenc + (size_t)(1024 + kz * 512) * 4096 + p * 64,
                  512, As, Ws, sG, tid);
        // write partial [col][b] coalesced
        float* dst = g_partG[kz] + (size_t)p * 64 * 64;
#pragma unroll
        for (int i = 0; i < 16; ++i) {
            int idx = tid + i * 256;
            dst[idx] = sG[idx >> 6][idx & 63];
        }
        grid_sync();
        // cell: this CTA owns n' in [bid*32, bid*32+32) -> j in [bid*8, bid*8+8)
#pragma unroll
        for (int r = 0; r < 2; ++r) {
            int id = tid + 256 * r;
            int b = id & 63, jj = id >> 6;
            int np = bid * 32 + 4 * jj;
            int j  = bid * 8 + jj;
            const float* p0 = g_partG[0] + (size_t)np * 64 + b;
            const float* p1 = g_partG[1] + (size_t)np * 64 + b;
            const float* gx = g_gatesX + ((size_t)t * 4096 + np) * 64 + b;
            float4 bb = *(const float4*)&g_bpe[np];
            float gi = p0[0]   + p1[0]   + gx[0]   + bb.x;
            float gf = p0[64]  + p1[64]  + gx[64]  + bb.y;
            float gg = p0[128] + p1[128] + gx[128] + bb.z;
            float go = p0[192] + p1[192] + gx[192] + bb.w;
            float c  = g_c[j * 64 + b];
            float cn = sigf(gf) * c + sigf(gi) * tanhf(gg);
            float hn = sigf(go) * tanhf(cn);
            g_c[j * 64 + b] = cn;
            g_dAT[cur ^ 1][(1024 + j) * 64 + b] = hn;
            if (t == SS - 1)   // stage dec_inp0 = x[:, -1, :]  (one-time scattered read)
                g_dAT[cur ^ 1][j * 64 + b] = x[((size_t)b * SS + SS - 1) * 1024 + j];
        }
        grid_sync();
        cur ^= 1;
    }

    // ---------------- decoder ----------------
    for (int t = 0; t < SS; ++t) {
        gemm_gate(g_dAT[cur] + (size_t)(kz * 1024) * 64,
                  g_WTdec + (size_t)(kz * 1024) * 4096 + p * 64,
                  1024, As, Ws, sG, tid);
        float* dst = g_partG[kz] + (size_t)p * 64 * 64;
#pragma unroll
        for (int i = 0; i < 16; ++i) {
            int idx = tid + i * 256;
            dst[idx] = sG[idx >> 6][idx & 63];
        }
        grid_sync();
#pragma unroll
        for (int r = 0; r < 2; ++r) {
            int id = tid + 256 * r;
            int b = id & 63, jj = id >> 6;
            int np = bid * 32 + 4 * jj;
            int j  = bid * 8 + jj;
            const float* p0 = g_partG[0] + (size_t)np * 64 + b;
            const float* p1 = g_partG[1] + (size_t)np * 64 + b;
            float4 bb = *(const float4*)&g_bpd[np];
            float gi = p0[0]   + p1[0]   + bb.x;
            float gf = p0[64]  + p1[64]  + bb.y;
            float gg = p0[128] + p1[128] + bb.z;
            float go = p0[192] + p1[192] + bb.w;
            float c  = g_c[j * 64 + b];
            float cn = sigf(gf) * c + sigf(gi) * tanhf(gg);
            float hn = sigf(go) * tanhf(cn);
            g_c[j * 64 + b] = cn;
            g_dAT[cur ^ 1][(1024 + j) * 64 + b] = hn;
        }
        grid_sync();   // h complete before fc reads full K

        gemm_fc(g_dAT[cur ^ 1] + (size_t)(1024 + kz * 512) * 64,
                g_WTfc + (size_t)(kz * 512) * 1024 + p * 16,
                512, As, Ws, sG, tid);
        {
            float* dstF = g_partF[kz] + (size_t)p * 16 * 64;
#pragma unroll
            for (int i = 0; i < 4; ++i) {
                int idx = tid + i * 256;
                dstF[idx] = sG[idx >> 6][idx & 63];
            }
        }
        grid_sync();
        // select: this CTA owns n in [bid*8, bid*8+8)
        int mk = g_mask[t];
#pragma unroll
        for (int r = 0; r < 2; ++r) {
            int id = tid + 256 * r;
            int b = id & 63, cc = id >> 6;
            int n = bid * 8 + cc;
            float v = g_partF[0][(size_t)n * 64 + b] + g_partF[1][(size_t)n * 64 + b] + fc_b[n];
            size_t oidx = ((size_t)b * SS + t) * 1024 + n;
            out[oidx] = v;
            g_dAT[cur ^ 1][n * 64 + b] = mk ? target[oidx] : v;
        }
        grid_sync();
        cur ^= 1;
    }
}

// ============ pre-GEMM: gatesX[t][n'][b] = x[b,t,:] @ packed Wih^T ============
// A rows are b-major in x -> transpose staging with XOR swizzle (self-contained).
__device__ __forceinline__ void storeAT(float* As, const float4 pa[2], int tid)
{
    const int k4 = tid & 7;
    const int mA = tid >> 3;
#pragma unroll
    for (int i = 0; i < 2; ++i) {
        int m  = mA + 32 * i;
        int cm = m >> 2;
        const float* e = (const float*)&pa[i];
#pragma unroll
        for (int r = 0; r < 4; ++r) {
            int k = k4 * 4 + r;
            As[k * 64 + ((cm ^ (k >> 2)) << 2) + (m & 3)] = e[r];
        }
    }
}

__global__ __launch_bounds__(256)
void gemm256(const float* __restrict__ x, const float* __restrict__ W,
             float* __restrict__ C)
{
    __shared__ __align__(16) float As[32 * 64];
    __shared__ __align__(16) float Ws[32 * 64];
    __shared__ __align__(16) float sG[64][65];

    const int tid = threadIdx.x;
    const int nBase = blockIdx.x * 64;
    const int tt    = blockIdx.y;
    const int ty = tid >> 5, tx = tid & 31;
    const int k4 = tid & 7, mA = tid >> 3;

    ull acc[4][2];
#pragma unroll
    for (int q = 0; q < 4; ++q) { acc[q][0] = 0ull; acc[q][1] = 0ull; }

    const float* rp0 = x + ((size_t)mA        * SS + tt) * 1024;
    const float* rp1 = x + ((size_t)(mA + 32) * SS + tt) * 1024;

    float4 pa[2], pw[2];
    pa[0] = *(const float4*)(rp0 + k4 * 4);
    pa[1] = *(const float4*)(rp1 + k4 * 4);
#pragma unroll
    for (int i = 0; i < 2; ++i) {
        int idx = tid + i * 256;
        pw[i] = *(const float4*)(W + (size_t)(idx >> 4) * 4096 + nBase + (idx & 15) * 4);
    }

    for (int kt = 0; kt < 1024; kt += 32) {
        storeAT(As, pa, tid);
#pragma unroll
        for (int i = 0; i < 2; ++i) {
            int idx = tid + i * 256;
            *(float4*)&Ws[(idx >> 4) * 64 + (idx & 15) * 4] = pw[i];
        }
        __syncthreads();
        if (kt + 32 < 1024) {
            pa[0] = *(const float4*)(rp0 + kt + 32 + k4 * 4);
            pa[1] = *(const float4*)(rp1 + kt + 32 + k4 * 4);
#pragma unroll
            for (int i = 0; i < 2; ++i) {
                int idx = tid + i * 256;
                pw[i] = *(const float4*)(W + (size_t)(kt + 32 + (idx >> 4)) * 4096 + nBase + (idx & 15) * 4);
            }
        }
#pragma unroll
        for (int kk = 0; kk < 32; ++kk) {
            int sw = kk >> 2;
            ulonglong2 aa = *(const ulonglong2*)&As[kk * 64 + (((2 * ty)     ^ sw) << 2)];
            ulonglong2 ab = *(const ulonglong2*)&As[kk * 64 + ((((2 * ty) | 1) ^ sw) << 2)];
            float2 wv = *(const float2*)&Ws[kk * 64 + 2 * tx];
            ull w0 = dup2(wv.x), w1 = dup2(wv.y);
            fma2(acc[0][0], aa.x, w0); fma2(acc[0][1], aa.x, w1);
            fma2(acc[1][0], aa.y, w0); fma2(acc[1][1], aa.y, w1);
            fma2(acc[2][0], ab.x, w0); fma2(acc[2][1], ab.x, w1);
            fma2(acc[3][0], ab.y, w0); fma2(acc[3][1], ab.y, w1);
        }
        __syncthreads();
    }
#pragma unroll
    for (int q = 0; q < 4; ++q) {
        float2 c0 = unpack2(acc[q][0]);
        float2 c1 = unpack2(acc[q][1]);
        int m = ty * 8 + 2 * q;
        sG[m][2 * tx]         = c0.x;
        sG[m][2 * tx + 1]     = c1.x;
        sG[m + 1][2 * tx]     = c0.y;
        sG[m + 1][2 * tx + 1] = c1.y;
    }
    __syncthreads();
#pragma unroll
    for (int rr = 0; rr < 4; ++rr) {
        int col = rr * 16 + (tid >> 4);
        int b4  = (tid & 15) * 4;
        float4 v = make_float4(sG[b4][col], sG[b4 + 1][col], sG[b4 + 2][col], sG[b4 + 3][col]);
        *(float4*)&C[((size_t)tt * 4096 + nBase + col) * 64 + b4] = v;
    }
}

// ---- fused transposes: z<4 gate-packed 4096-col, z==4 plain fc ----
__global__ void tposeAll(const float* __restrict__ eWih, const float* __restrict__ eWhh,
                         const float* __restrict__ dWih, const float* __restrict__ dWhh,
                         const float* __restrict__ fcW)
{
    __shared__ float t[32][33];
    int z = blockIdx.z;
    int k0 = blockIdx.x * 32, n0 = blockIdx.y * 32;
    if (z == 4) {
        if (blockIdx.y >= 32) return;
        float* dst = g_WTfc;
#pragma unroll
        for (int i = 0; i < 32; i += 8)
            t[threadIdx.y + i][threadIdx.x] = fcW[(size_t)(n0 + threadIdx.y + i) * 1024 + k0 + threadIdx.x];
        __syncthreads();
#pragma unroll
        for (int i = 0; i < 32; i += 8)
            dst[(size_t)(k0 + threadIdx.y + i) * 1024 + n0 + threadIdx.x] = t[threadIdx.x][threadIdx.y + i];
        return;
    }
    const float* src = (z == 0) ? eWih : (z == 1) ? eWhh : (z == 2) ? dWih : dWhh;
    float* dst = (z < 2) ? (g_WTenc + (size_t)(z & 1) * 1024 * 4096)
                         : (g_WTdec + (size_t)(z & 1) * 1024 * 4096);
#pragma unroll
    for (int i = 0; i < 32; i += 8) {
        int np  = n0 + threadIdx.y + i;
        int row = ((np & 3) << 10) + (np >> 2);
        t[threadIdx.y + i][threadIdx.x] = src[(size_t)row * 1024 + k0 + threadIdx.x];
    }
    __syncthreads();
#pragma unroll
    for (int i = 0; i < 32; i += 8)
        dst[(size_t)(k0 + threadIdx.y + i) * 4096 + n0 + threadIdx.x] = t[threadIdx.x][threadIdx.y + i];
}

// ---------------- tf_mask layout probe + decode ----------------
__global__ void mask_decode(const unsigned char* __restrict__ p)
{
    __shared__ int s_odd, s_big;
    int t = threadIdx.x;
    if (t == 0) { s_odd = 0; s_big = 0; }
    __syncthreads();
    unsigned char v = p[t];
    if ((t & 3) && v)  atomicOr(&s_odd, 1);
    if (v > 1)         atomicOr(&s_big, 1);
    __syncthreads();
    int m;
    if (s_big)        m = (((const float*)p)[t] != 0.0f);
    else if (s_odd)   m = (p[t] != 0);
    else              m = (((const int*)p)[t] != 0);
    g_mask[t] = m;
}

// ---------------- init: zero states, pack biases, reset barrier ----------------
__global__ void init_state(const float* __restrict__ enc_b, const float* __restrict__ dec_b)
{
    int i = blockIdx.x * blockDim.x + threadIdx.x;   // 65536
    g_c[i] = 0.0f;
    g_dAT[0][i] = 0.0f;
    g_dAT[0][i + 65536] = 0.0f;
    if (i < 4096) {
        int row = ((i & 3) << 10) + (i >> 2);
        g_bpe[i] = enc_b[row];
        g_bpd[i] = dec_b[row];
    }
    if (i == 0) { g_barCount = 0u; g_barGen = 0u; }
}

__global__ void dummy_pad() { }

// ---------------- host ----------------
extern "C" void kernel_launch(void* const* d_in, const int* in_sizes, int n_in,
                              void* d_out, int out_size)
{
    (void)in_sizes; (void)n_in; (void)out_size;
    const float* x       = (const float*)d_in[0];
    const float* target  = (const float*)d_in[1];
    const float* enc_Wih = (const float*)d_in[2];
    const float* enc_Whh = (const float*)d_in[3];
    const float* enc_b   = (const float*)d_in[4];
    const float* dec_Wih = (const float*)d_in[5];
    const float* dec_Whh = (const float*)d_in[6];
    const float* dec_b   = (const float*)d_in[7];
    const float* fc_W    = (const float*)d_in[8];
    const float* fc_b    = (const float*)d_in[9];
    const unsigned char* tf_mask = (const unsigned char*)d_in[10];
    float* out = (float*)d_out;

    float *pWTenc, *pGatesX;
    cudaGetSymbolAddress((void**)&pWTenc,  g_WTenc);
    cudaGetSymbolAddress((void**)&pGatesX, g_gatesX);

    // launch #1
    mask_decode<<<1, 512>>>(tf_mask);
    // launch #2 (all five transposes fused)
    tposeAll<<<dim3(32, 128, 5), dim3(32, 8)>>>(enc_Wih, enc_Whh, dec_Wih, dec_Whh, fc_W);
    // launch #3
    init_state<<<256, 256>>>(enc_b, dec_b);
    // launch #4: gatesX[t][n'][b]
    gemm256<<<dim3(64, 512), 256>>>(x, pWTenc, pGatesX);
    // launch #5: pad so ncu (-s 5 -c 1) profiles the persistent kernel
    dummy_pad<<<1, 32>>>();
    // launch #6: the persistent recurrence
    seq2seq_persist<<<NBLK, 256>>>(x, target, fc_b, out);
}

// round 7
// speedup vs baseline: 1.6203x; 1.1395x over previous
#include <cuda_runtime.h>
#include <math.h>
#include <stdint.h>

typedef unsigned long long ull;

#define SS 512
#define NBLK 128

// ---------------- device scratch (no allocations allowed) ----------------
__device__ float g_WTenc[2048 * 4096];   // packed [k][n'=4j+g]; rows 0..1023 = Wih, 1024..2047 = Whh
__device__ float g_WTdec[2048 * 4096];   // same packing
__device__ float g_WTfc [1024 * 1024];   // plain [k][n]
__device__ float g_gatesX[(size_t)512 * 4096 * 64]; // [t][n'][b]  (512MB)
__device__ float g_dAT[2][2048 * 64];    // ping-pong, [k][b]: k 0..1023 = inp, 1024..2047 = h
__device__ float g_c  [1024 * 64];       // [j][b]
__device__ float g_partG[4][4096 * 64];  // gate partials [kz][n'][b]
__device__ float g_bpe[4096], g_bpd[4096];
__device__ int   g_mask[512];
__device__ unsigned           g_barLeaf[16 * 32];   // one leaf per 128B line
__device__ unsigned           g_barRoot;
__device__ volatile unsigned  g_barGen;

// ---------------- f32x2 helpers ----------------
__device__ __forceinline__ ull dup2(float v) {
    ull r; unsigned u = __float_as_uint(v);
    asm("mov.b64 %0, {%1, %1};" : "=l"(r) : "r"(u));
    return r;
}
__device__ __forceinline__ void fma2(ull& acc, ull a, ull b) {
    asm("fma.rn.f32x2 %0, %1, %2, %0;" : "+l"(acc) : "l"(a), "l"(b));
}
__device__ __forceinline__ ull add2(ull a, ull b) {
    ull r; asm("add.rn.f32x2 %0, %1, %2;" : "=l"(r) : "l"(a), "l"(b)); return r;
}
__device__ __forceinline__ float2 unpack2(ull v) {
    unsigned lo, hi;
    asm("mov.b64 {%0, %1}, %2;" : "=r"(lo), "=r"(hi) : "l"(v));
    return make_float2(__uint_as_float(lo), __uint_as_float(hi));
}
__device__ __forceinline__ float sigf(float x) { return 1.0f / (1.0f + expf(-x)); }

// ---------------- grid barrier: padded-leaf tree arrival + volatile poll ----------------
__device__ __forceinline__ void grid_sync(unsigned n) {
    __syncthreads();
    if (threadIdx.x == 0) {
        __threadfence();
        unsigned leaf = (blockIdx.x >> 3) * 32;          // 16 leaves, 128B apart
        if (atomicAdd(&g_barLeaf[leaf], 1u) + 1u == n * 8u) {
            if (atomicAdd(&g_barRoot, 1u) + 1u == n * 16u) {
                g_barGen = n;
            }
        }
        while (g_barGen < n) { }
        __threadfence();
    }
    __syncthreads();
}

// ============ gate GEMM: tile 64b x 128n, per-CTA K-slice, direct partial store ============
// 256 threads: ty=tid>>5 -> 8 b (4 pairs), tx=tid&31 -> 4 cols. 16 fma2/kk.
__device__ __forceinline__ void gemm_gate(const float* __restrict__ A,    // [k][64] at slice base
                                          const float* __restrict__ Wp,  // + row/col offsets, ldw 4096
                                          int nKT,
                                          float* As, float* Ws,
                                          float* __restrict__ dst,        // g_partG[kz] + p*128*64
                                          int tid)
{
    const int ty = tid >> 5, tx = tid & 31;
    ull acc[4][4];
#pragma unroll
    for (int q = 0; q < 4; ++q)
#pragma unroll
        for (int c = 0; c < 4; ++c) acc[q][c] = 0ull;

    float4 pa[2], pw[4];
#pragma unroll
    for (int i = 0; i < 2; ++i) {
        int idx = tid + i * 256;
        pa[i] = *(const float4*)(A + (size_t)(idx >> 4) * 64 + (idx & 15) * 4);
    }
#pragma unroll
    for (int i = 0; i < 4; ++i) {
        int idx = tid + i * 256;
        pw[i] = *(const float4*)(Wp + (size_t)(idx >> 5) * 4096 + (idx & 31) * 4);
    }

    for (int kt = 0; kt < nKT; ++kt) {
#pragma unroll
        for (int i = 0; i < 2; ++i) {
            int idx = tid + i * 256;
            *(float4*)&As[(idx >> 4) * 64 + (idx & 15) * 4] = pa[i];
        }
#pragma unroll
        for (int i = 0; i < 4; ++i) {
            int idx = tid + i * 256;
            *(float4*)&Ws[(idx >> 5) * 128 + (idx & 31) * 4] = pw[i];
        }
        __syncthreads();
        if (kt + 1 < nKT) {
            int kOff = (kt + 1) * 32;
#pragma unroll
            for (int i = 0; i < 2; ++i) {
                int idx = tid + i * 256;
                pa[i] = *(const float4*)(A + (size_t)(kOff + (idx >> 4)) * 64 + (idx & 15) * 4);
            }
#pragma unroll
            for (int i = 0; i < 4; ++i) {
                int idx = tid + i * 256;
                pw[i] = *(const float4*)(Wp + (size_t)(kOff + (idx >> 5)) * 4096 + (idx & 31) * 4);
            }
        }
#pragma unroll
        for (int kk = 0; kk < 32; ++kk) {
            ulonglong2 aa = *(const ulonglong2*)&As[kk * 64 + 8 * ty];
            ulonglong2 ab = *(const ulonglong2*)&As[kk * 64 + 8 * ty + 4];
            float4 wv = *(const float4*)&Ws[kk * 128 + 4 * tx];
            ull w0 = dup2(wv.x), w1 = dup2(wv.y), w2 = dup2(wv.z), w3 = dup2(wv.w);
            fma2(acc[0][0], aa.x, w0); fma2(acc[0][1], aa.x, w1);
            fma2(acc[0][2], aa.x, w2); fma2(acc[0][3], aa.x, w3);
            fma2(acc[1][0], aa.y, w0); fma2(acc[1][1], aa.y, w1);
            fma2(acc[1][2], aa.y, w2); fma2(acc[1][3], aa.y, w3);
            fma2(acc[2][0], ab.x, w0); fma2(acc[2][1], ab.x, w1);
            fma2(acc[2][2], ab.x, w2); fma2(acc[2][3], ab.x, w3);
            fma2(acc[3][0], ab.y, w0); fma2(acc[3][1], ab.y, w1);
            fma2(acc[3][2], ab.y, w2); fma2(acc[3][3], ab.y, w3);
        }
        __syncthreads();
    }
    // direct store: dst[(localcol)*64 + b], float2 over b-pair
#pragma unroll
    for (int q = 0; q < 4; ++q)
#pragma unroll
        for (int c = 0; c < 4; ++c) {
            float2 v = unpack2(acc[q][c]);
            *(float2*)&dst[(4 * tx + c) * 64 + 8 * ty + 2 * q] = v;
        }
}

// ============ fc GEMM full-K (64b x 8n per CTA) with fused select epilogue ============
__device__ __forceinline__ void fc_select(const float* __restrict__ A,   // h: [k][64], K=1024
                                          const float* __restrict__ Wp, // g_WTfc + bid*8
                                          const float* __restrict__ fc_b,
                                          const float* __restrict__ target,
                                          float* __restrict__ out,
                                          float* __restrict__ dA1,
                                          int t, int bid, int mk,
                                          float* As, float* Ws, int tid)
{
    const int ty = tid >> 3;   // b-pair 0..31
    const int tx = tid & 7;    // col
    ull acc[4];
#pragma unroll
    for (int i = 0; i < 4; ++i) acc[i] = 0ull;

    float4 pa[2], pw;
#pragma unroll
    for (int i = 0; i < 2; ++i) {
        int idx = tid + i * 256;
        pa[i] = *(const float4*)(A + (size_t)(idx >> 4) * 64 + (idx & 15) * 4);
    }
    if (tid < 64)
        pw = *(const float4*)(Wp + (size_t)(tid >> 1) * 1024 + (tid & 1) * 4);

    for (int kt = 0; kt < 32; ++kt) {
#pragma unroll
        for (int i = 0; i < 2; ++i) {
            int idx = tid + i * 256;
            *(float4*)&As[(idx >> 4) * 64 + (idx & 15) * 4] = pa[i];
        }
        if (tid < 64) *(float4*)&Ws[(tid >> 1) * 8 + (tid & 1) * 4] = pw;
        __syncthreads();
        if (kt + 1 < 32) {
            int kOff = (kt + 1) * 32;
#pragma unroll
            for (int i = 0; i < 2; ++i) {
                int idx = tid + i * 256;
                pa[i] = *(const float4*)(A + (size_t)(kOff + (idx >> 4)) * 64 + (idx & 15) * 4);
            }
            if (tid < 64)
                pw = *(const float4*)(Wp + (size_t)(kOff + (tid >> 1)) * 1024 + (tid & 1) * 4);
        }
#pragma unroll
        for (int kk = 0; kk < 32; ++kk) {
            ull a = *(const ull*)&As[kk * 64 + 2 * ty];
            fma2(acc[kk & 3], a, dup2(Ws[kk * 8 + tx]));
        }
        __syncthreads();
    }
    ull s = add2(add2(acc[0], acc[1]), add2(acc[2], acc[3]));
    float2 v = unpack2(s);
    int n = bid * 8 + tx;
    float vb = fc_b[n];
    int b0 = 2 * ty;
    float p0 = v.x + vb, p1 = v.y + vb;
    size_t o0 = ((size_t)b0 * SS + t) * 1024 + n;
    size_t o1 = o0 + (size_t)SS * 1024;
    out[o0] = p0;
    out[o1] = p1;
    dA1[n * 64 + b0]     = mk ? target[o0] : p0;
    dA1[n * 64 + b0 + 1] = mk ? target[o1] : p1;
}

// ============ the persistent seq2seq kernel ============
__global__ __launch_bounds__(256, 1)
void seq2seq_persist(const float* __restrict__ x, const float* __restrict__ target,
                     const float* __restrict__ fc_b, float* __restrict__ out)
{
    __shared__ __align__(16) float As[32 * 64];
    __shared__ __align__(16) float Ws[32 * 128];

    const int tid = threadIdx.x;
    const int bid = blockIdx.x;
    const int p   = bid >> 2;     // n-tile (128 cols)
    const int kz  = bid & 3;      // K quarter
    int cur = 0;
    unsigned ns = 0;

    // ---------------- encoder (gate K=1024, h only; x-part precomputed) ----------------
    for (int t = 0; t < SS; ++t) {
        gemm_gate(g_dAT[cur] + (size_t)(1024 + kz * 256) * 64,
                  g_WTenc + (size_t)(1024 + kz * 256) * 4096 + p * 128,
                  8, As, Ws, g_partG[kz] + (size_t)p * 128 * 64, tid);
        grid_sync(++ns);
#pragma unroll
        for (int r = 0; r < 2; ++r) {
            int id = tid + 256 * r;
            int b = id & 63, jj = id >> 6;
            int np = bid * 32 + 4 * jj;
            int j  = bid * 8 + jj;
            const float* q0 = g_partG[0] + (size_t)np * 64 + b;
            const float* q1 = g_partG[1] + (size_t)np * 64 + b;
            const float* q2 = g_partG[2] + (size_t)np * 64 + b;
            const float* q3 = g_partG[3] + (size_t)np * 64 + b;
            const float* gx = g_gatesX + ((size_t)t * 4096 + np) * 64 + b;
            float4 bb = *(const float4*)&g_bpe[np];
            float gi = q0[0]   + q1[0]   + q2[0]   + q3[0]   + gx[0]   + bb.x;
            float gf = q0[64]  + q1[64]  + q2[64]  + q3[64]  + gx[64]  + bb.y;
            float gg = q0[128] + q1[128] + q2[128] + q3[128] + gx[128] + bb.z;
            float go = q0[192] + q1[192] + q2[192] + q3[192] + gx[192] + bb.w;
            float c  = g_c[j * 64 + b];
            float cn = sigf(gf) * c + sigf(gi) * tanhf(gg);
            float hn = sigf(go) * tanhf(cn);
            g_c[j * 64 + b] = cn;
            g_dAT[cur ^ 1][(1024 + j) * 64 + b] = hn;
            if (t == SS - 1)   // stage dec_inp0 = x[:, -1, :]
                g_dAT[cur ^ 1][j * 64 + b] = x[((size_t)b * SS + SS - 1) * 1024 + j];
        }
        grid_sync(++ns);
        cur ^= 1;
    }

    // ---------------- decoder (gate K=2048) ----------------
    for (int t = 0; t < SS; ++t) {
        gemm_gate(g_dAT[cur] + (size_t)(kz * 512) * 64,
                  g_WTdec + (size_t)(kz * 512) * 4096 + p * 128,
                  16, As, Ws, g_partG[kz] + (size_t)p * 128 * 64, tid);
        grid_sync(++ns);
#pragma unroll
        for (int r = 0; r < 2; ++r) {
            int id = tid + 256 * r;
            int b = id & 63, jj = id >> 6;
            int np = bid * 32 + 4 * jj;
            int j  = bid * 8 + jj;
            const float* q0 = g_partG[0] + (size_t)np * 64 + b;
            const float* q1 = g_partG[1] + (size_t)np * 64 + b;
            const float* q2 = g_partG[2] + (size_t)np * 64 + b;
            const float* q3 = g_partG[3] + (size_t)np * 64 + b;
            float4 bb = *(const float4*)&g_bpd[np];
            float gi = q0[0]   + q1[0]   + q2[0]   + q3[0]   + bb.x;
            float gf = q0[64]  + q1[64]  + q2[64]  + q3[64]  + bb.y;
            float gg = q0[128] + q1[128] + q2[128] + q3[128] + bb.z;
            float go = q0[192] + q1[192] + q2[192] + q3[192] + bb.w;
            float c  = g_c[j * 64 + b];
            float cn = sigf(gf) * c + sigf(gi) * tanhf(gg);
            float hn = sigf(go) * tanhf(cn);
            g_c[j * 64 + b] = cn;
            g_dAT[cur ^ 1][(1024 + j) * 64 + b] = hn;
        }
        grid_sync(++ns);   // h complete before fc reads full K
        fc_select(g_dAT[cur ^ 1] + (size_t)1024 * 64, g_WTfc + bid * 8,
                  fc_b, target, out, g_dAT[cur ^ 1], t, bid, g_mask[t], As, Ws, tid);
        grid_sync(++ns);   // inp visible before next gate GEMM
        cur ^= 1;
    }
}

// ============ pre-GEMM: gatesX[t][n'][b] = x[b,t,:] @ packed Wih^T ============
// tile 128m x 128n (m = 2 timesteps x 64 batch), per-thread 8x8 = 32 fma2/kk
__global__ __launch_bounds__(256, 1)
void gemm_pre(const float* __restrict__ x, const float* __restrict__ W,
              float* __restrict__ C)
{
    __shared__ __align__(16) float As[32 * 128];   // [k][m] swizzled
    __shared__ __align__(16) float Ws[32 * 128];   // [k][n]

    const int tid = threadIdx.x;
    const int nBase = blockIdx.x * 128;
    const int tp    = blockIdx.y;          // t-pair
    const int tyy = tid >> 4;              // 0..15 -> pairs {tyy, tyy+16, tyy+32, tyy+48}
    const int tx  = tid & 15;              // cols 8*tx .. 8*tx+7

    ull acc[4][8];
#pragma unroll
    for (int s = 0; s < 4; ++s)
#pragma unroll
        for (int c = 0; c < 8; ++c) acc[s][c] = 0ull;

    // row pointers for the 4 A-load rows this thread stages
    const float* rp[4];
#pragma unroll
    for (int i = 0; i < 4; ++i) {
        int idx = tid + i * 256;
        int mA = idx >> 3;
        int b = mA & 63, tsel = mA >> 6;
        rp[i] = x + ((size_t)b * SS + 2 * tp + tsel) * 1024;
    }
    const int k4 = tid & 7;

    float4 pa[4], pw[4];
#pragma unroll
    for (int i = 0; i < 4; ++i) {
        pa[i] = *(const float4*)(rp[i] + k4 * 4);
        int idx = tid + i * 256;
        pw[i] = *(const float4*)(W + (size_t)(idx >> 5) * 4096 + nBase + (idx & 31) * 4);
    }

    for (int kt = 0; kt < 32; ++kt) {
#pragma unroll
        for (int i = 0; i < 4; ++i) {
            int idx = tid + i * 256;
            int m = idx >> 3;
            int cm = m >> 2;
            const float* e = (const float*)&pa[i];
#pragma unroll
            for (int r = 0; r < 4; ++r) {
                int k = k4 * 4 + r;
                As[k * 128 + ((cm ^ (k >> 2)) << 2) + (m & 3)] = e[r];
            }
            *(float4*)&Ws[(idx >> 5) * 128 + (idx & 31) * 4] = pw[i];
        }
        __syncthreads();
        if (kt + 1 < 32) {
            int kOff = (kt + 1) * 32;
#pragma unroll
            for (int i = 0; i < 4; ++i) {
                pa[i] = *(const float4*)(rp[i] + kOff + k4 * 4);
                int idx = tid + i * 256;
                pw[i] = *(const float4*)(W + (size_t)(kOff + (idx >> 5)) * 4096 + nBase + (idx & 31) * 4);
            }
        }
#pragma unroll
        for (int kk = 0; kk < 32; ++kk) {
            int sw = kk >> 2;
            ull a[4];
#pragma unroll
            for (int s = 0; s < 4; ++s) {
                int r = tyy + 16 * s;
                a[s] = *(const ull*)&As[kk * 128 + (((r >> 1) ^ sw) << 2) + 2 * (r & 1)];
            }
            float4 wA = *(const float4*)&Ws[kk * 128 + 8 * tx];
            float4 wB = *(const float4*)&Ws[kk * 128 + 8 * tx + 4];
            ull w[8];
            w[0] = dup2(wA.x); w[1] = dup2(wA.y); w[2] = dup2(wA.z); w[3] = dup2(wA.w);
            w[4] = dup2(wB.x); w[5] = dup2(wB.y); w[6] = dup2(wB.z); w[7] = dup2(wB.w);
#pragma unroll
            for (int s = 0; s < 4; ++s)
#pragma unroll
                for (int c = 0; c < 8; ++c)
                    fma2(acc[s][c], a[s], w[c]);
        }
        __syncthreads();
    }
    // direct store: C[((t*4096)+col)*64 + b], float2 over b-pair
#pragma unroll
    for (int s = 0; s < 4; ++s) {
        int r = tyy + 16 * s;
        int m = 2 * r;
        int b = m & 63, tsel = m >> 6;
        size_t tb = ((size_t)(2 * tp + tsel) * 4096 + nBase + 8 * tx) * 64 + b;
#pragma unroll
        for (int c = 0; c < 8; ++c) {
            float2 v = unpack2(acc[s][c]);
            *(float2*)&C[tb + (size_t)c * 64] = v;
        }
    }
}

// ---- fused transposes: z<4 gate-packed 4096-col, z==4 plain fc ----
__global__ void tposeAll(const float* __restrict__ eWih, const float* __restrict__ eWhh,
                         const float* __restrict__ dWih, const float* __restrict__ dWhh,
                         const float* __restrict__ fcW)
{
    __shared__ float t[32][33];
    int z = blockIdx.z;
    int k0 = blockIdx.x * 32, n0 = blockIdx.y * 32;
    if (z == 4) {
        if (blockIdx.y >= 32) return;
#pragma unroll
        for (int i = 0; i < 32; i += 8)
            t[threadIdx.y + i][threadIdx.x] = fcW[(size_t)(n0 + threadIdx.y + i) * 1024 + k0 + threadIdx.x];
        __syncthreads();
#pragma unroll
        for (int i = 0; i < 32; i += 8)
            g_WTfc[(size_t)(k0 + threadIdx.y + i) * 1024 + n0 + threadIdx.x] = t[threadIdx.x][threadIdx.y + i];
        return;
    }
    const float* src = (z == 0) ? eWih : (z == 1) ? eWhh : (z == 2) ? dWih : dWhh;
    float* dst = (z < 2) ? (g_WTenc + (size_t)(z & 1) * 1024 * 4096)
                         : (g_WTdec + (size_t)(z & 1) * 1024 * 4096);
#pragma unroll
    for (int i = 0; i < 32; i += 8) {
        int np  = n0 + threadIdx.y + i;
        int row = ((np & 3) << 10) + (np >> 2);
        t[threadIdx.y + i][threadIdx.x] = src[(size_t)row * 1024 + k0 + threadIdx.x];
    }
    __syncthreads();
#pragma unroll
    for (int i = 0; i < 32; i += 8)
        dst[(size_t)(k0 + threadIdx.y + i) * 4096 + n0 + threadIdx.x] = t[threadIdx.x][threadIdx.y + i];
}

// ---------------- init + mask decode (fused, 128x512) ----------------
__global__ void mask_init(const unsigned char* __restrict__ p,
                          const float* __restrict__ enc_b, const float* __restrict__ dec_b)
{
    int tid = threadIdx.x;
    int i = blockIdx.x * 512 + tid;     // 0..65535
    g_c[i] = 0.0f;
    g_dAT[0][i] = 0.0f;
    g_dAT[0][i + 65536] = 0.0f;
    if (i < 4096) {
        int row = ((i & 3) << 10) + (i >> 2);
        g_bpe[i] = enc_b[row];
        g_bpd[i] = dec_b[row];
    }
    if (blockIdx.x == 1) {
        g_barLeaf[tid] = 0u;              // 512 entries
        if (tid == 0) { g_barRoot = 0u; g_barGen = 0u; }
    }
    if (blockIdx.x == 0) {
        __shared__ int s_odd, s_big;
        if (tid == 0) { s_odd = 0; s_big = 0; }
        __syncthreads();
        unsigned char v = p[tid];
        if ((tid & 3) && v)  atomicOr(&s_odd, 1);
        if (v > 1)           atomicOr(&s_big, 1);
        __syncthreads();
        int m;
        if (s_big)        m = (((const float*)p)[tid] != 0.0f);
        else if (s_odd)   m = (p[tid] != 0);
        else              m = (((const int*)p)[tid] != 0);
        g_mask[tid] = m;
    }
}

// ---------------- host ----------------
extern "C" void kernel_launch(void* const* d_in, const int* in_sizes, int n_in,
                              void* d_out, int out_size)
{
    (void)in_sizes; (void)n_in; (void)out_size;
    const float* x       = (const float*)d_in[0];
    const float* target  = (const float*)d_in[1];
    const float* enc_Wih = (const float*)d_in[2];
    const float* enc_Whh = (const float*)d_in[3];
    const float* enc_b   = (const float*)d_in[4];
    const float* dec_Wih = (const float*)d_in[5];
    const float* dec_Whh = (const float*)d_in[6];
    const float* dec_b   = (const float*)d_in[7];
    const float* fc_W    = (const float*)d_in[8];
    const float* fc_b    = (const float*)d_in[9];
    const unsigned char* tf_mask = (const unsigned char*)d_in[10];
    float* out = (float*)d_out;

    float *pWTenc, *pGatesX;
    cudaGetSymbolAddress((void**)&pWTenc,  g_WTenc);
    cudaGetSymbolAddress((void**)&pGatesX, g_gatesX);

    // launch #1: init + mask decode
    mask_init<<<128, 512>>>(tf_mask, enc_b, dec_b);
    // launch #2: all five weight transposes
    tposeAll<<<dim3(32, 128, 5), dim3(32, 8)>>>(enc_Wih, enc_Whh, dec_Wih, dec_Whh, fc_W);
    // launch #3: gatesX[t][n'][b]  (128m x 128n tiles)
    gemm_pre<<<dim3(32, 256), 256>>>(x, pWTenc, pGatesX);
    // launch #4: the persistent recurrence (profiled by ncu -s 5 -c 1)
    seq2seq_persist<<<NBLK, 256>>>(x, target, fc_b, out);
}